// round 2
// baseline (speedup 1.0000x reference)
#include <cuda_runtime.h>
#include <math.h>

#define NSEQ   2048
#define DMODEL 1024
#define HEADS  16
#define DH     64
#define CTX    128
#define QT     64        // queries per block
#define LSTRIP 320       // key strip length (QT + 2*CTX, chunk-rounded)
#define SPAD   324       // padded S row stride (floats)
#define KVPAD  68        // padded K/V chunk row stride (floats)
#define NCHUNK 5
#define SCALE  0.125f    // 1/sqrt(64)

#define SMEM_FLOATS (QT*DH + 64*KVPAD + QT*SPAD + QT)
#define SMEM_BYTES  (SMEM_FLOATS * 4)

typedef unsigned long long u64;

union F4 { float4 f; u64 d[2]; };

// packed f32x2 FMA: acc.{lo,hi} += a.{lo,hi} * b.{lo,hi}
__device__ __forceinline__ void ffma2(u64& acc, u64 a, u64 b) {
    asm("fma.rn.f32x2 %0, %1, %2, %0;" : "+l"(acc) : "l"(a), "l"(b));
}
__device__ __forceinline__ u64 splat2(float x) {
    u64 r; unsigned u = __float_as_uint(x);
    asm("mov.b64 %0, {%1, %1};" : "=l"(r) : "r"(u));
    return r;
}
__device__ __forceinline__ float flo(u64 d) { return __uint_as_float((unsigned)d); }
__device__ __forceinline__ float fhi(u64 d) { return __uint_as_float((unsigned)(d >> 32)); }

// exp(x) for x <= 0 via FMA-pipe polynomial (avoids the 0.5/cyc/SM MUFU wall).
// |rel err| ~3e-6, far inside the 1e-3 budget.
__device__ __forceinline__ float fastexp(float x) {
    x = fmaxf(x, -80.0f);
    float y  = x * 1.4426950408889634f;          // log2(e)
    float t  = y + 12582912.0f;                  // round-to-nearest-int trick
    float fn = t - 12582912.0f;
    float f  = y - fn;                           // f in [-0.5, 0.5]
    int   n  = (int)fn;
    float p  = 1.3333558146e-3f;
    p = fmaf(p, f, 9.6181291076e-3f);
    p = fmaf(p, f, 5.5504108664e-2f);
    p = fmaf(p, f, 2.4022650696e-1f);
    p = fmaf(p, f, 6.9314718056e-1f);
    p = fmaf(p, f, 1.0f);
    return p * __int_as_float((n + 127) << 23);
}

__global__ void __launch_bounds__(256, 1)
sparse_attn_kernel(const float* __restrict__ qg, const float* __restrict__ kg,
                   const float* __restrict__ vg, float* __restrict__ og)
{
    extern __shared__ float sm[];
    float* Qs   = sm;                    // [QT][DH]           16 KB
    float* KV   = Qs + QT * DH;          // [64][KVPAD]        17 KB (K then V, per chunk)
    float* S    = KV + 64 * KVPAD;       // [QT][SPAD]         81 KB (scores -> probs)
    float* rinv = S + QT * SPAD;         // [QT] 1/rowsum

    const int h  = blockIdx.y;
    const int i0 = blockIdx.x * QT;
    const int j0 = i0 - CTX;             // strip covers keys [j0, j0+LSTRIP)
    const int t  = threadIdx.x;
    const int tx = t & 15, ty = t >> 4;
    const int row = ty * 4;              // this thread's 4 query rows
    const size_t hoff = (size_t)h * DH;

    // ---- load Q tile (coalesced) ----
    for (int idx = t; idx < QT * DH; idx += 256) {
        int r = idx >> 6, c = idx & 63;
        Qs[idx] = qg[(size_t)(i0 + r) * DMODEL + hoff + c];
    }

    // ---- QK: build score strip S[64][320] ----
    for (int ch = 0; ch < NCHUNK; ch++) {
        const int jc = j0 + ch * 64;
        const bool valid = (jc + 63 >= 0) && (jc < NSEQ);   // block-uniform
        __syncthreads();                                     // KV buffer reuse fence
        if (valid) {
            for (int idx = t; idx < 64 * 16; idx += 256) {   // float4 loads
                int r = idx >> 4, c4 = (idx & 15) * 4;
                int j = jc + r;
                float4 val = make_float4(0.f, 0.f, 0.f, 0.f);
                if (j >= 0 && j < NSEQ)
                    val = *(const float4*)&kg[(size_t)j * DMODEL + hoff + c4];
                *(float4*)&KV[r * KVPAD + c4] = val;
            }
        }
        __syncthreads();
        if (!valid) continue;

        u64 acc[4][4];
        #pragma unroll
        for (int i = 0; i < 4; i++)
            #pragma unroll
            for (int j = 0; j < 4; j++) acc[i][j] = 0ull;

        #pragma unroll
        for (int kk = 0; kk < DH; kk += 4) {
            F4 qv[4], kv[4];
            #pragma unroll
            for (int i = 0; i < 4; i++)
                qv[i].f = *(const float4*)&Qs[(row + i) * DH + kk];      // broadcast
            #pragma unroll
            for (int j = 0; j < 4; j++)
                kv[j].f = *(const float4*)&KV[(tx + 16 * j) * KVPAD + kk]; // conflict-free
            #pragma unroll
            for (int i = 0; i < 4; i++)
                #pragma unroll
                for (int j = 0; j < 4; j++) {
                    ffma2(acc[i][j], qv[i].d[0], kv[j].d[0]);
                    ffma2(acc[i][j], qv[i].d[1], kv[j].d[1]);
                }
        }
        #pragma unroll
        for (int i = 0; i < 4; i++)
            #pragma unroll
            for (int j = 0; j < 4; j++)
                S[(row + i) * SPAD + ch * 64 + tx + 16 * j] =
                    (flo(acc[i][j]) + fhi(acc[i][j])) * SCALE;
    }

    // ---- softmax over band (exact: out-of-band == 0, matching exp(-1e9)=0) ----
    __syncthreads();
    {
        const int wid = t >> 5, lane = t & 31;
        for (int rr = 0; rr < 8; rr++) {
            int r = wid * 8 + rr;
            int i = i0 + r;
            int jlo = max(0, i - CTX), jhi = min(NSEQ - 1, i + CTX);
            int clo = jlo - j0, chi = jhi - j0;
            float m = -1e30f;
            for (int c = clo + lane; c <= chi; c += 32)
                m = fmaxf(m, S[r * SPAD + c]);
            #pragma unroll
            for (int o = 16; o > 0; o >>= 1)
                m = fmaxf(m, __shfl_xor_sync(0xffffffffu, m, o));
            float ssum = 0.f;
            for (int c = lane; c < LSTRIP; c += 32) {
                float val = 0.f;
                if (c >= clo && c <= chi)
                    val = fastexp(S[r * SPAD + c] - m);
                S[r * SPAD + c] = val;         // S now holds unnormalized P
                ssum += val;
            }
            #pragma unroll
            for (int o = 16; o > 0; o >>= 1)
                ssum += __shfl_xor_sync(0xffffffffu, ssum, o);
            if (lane == 0) rinv[r] = 1.0f / ssum;
        }
    }

    // ---- PV: A[64][64] += P[64][320] * V[320][64], chunk by chunk ----
    u64 accd[4][2];
    #pragma unroll
    for (int i = 0; i < 4; i++) { accd[i][0] = 0ull; accd[i][1] = 0ull; }

    for (int ch = 0; ch < NCHUNK; ch++) {
        const int jc = j0 + ch * 64;
        const bool valid = (jc + 63 >= 0) && (jc < NSEQ);
        __syncthreads();
        if (valid) {
            for (int idx = t; idx < 64 * 16; idx += 256) {
                int r = idx >> 4, c4 = (idx & 15) * 4;
                int j = jc + r;
                float4 val = make_float4(0.f, 0.f, 0.f, 0.f);
                if (j >= 0 && j < NSEQ)
                    val = *(const float4*)&vg[(size_t)j * DMODEL + hoff + c4];
                *(float4*)&KV[r * KVPAD + c4] = val;
            }
        }
        __syncthreads();
        if (!valid) continue;

        #pragma unroll 4
        for (int c = 0; c < 64; c += 2) {
            F4 vlo, vhi;
            vlo.f = *(const float4*)&KV[c * KVPAD + 4 * tx];
            vhi.f = *(const float4*)&KV[(c + 1) * KVPAD + 4 * tx];
            #pragma unroll
            for (int i = 0; i < 4; i++) {
                u64 pp = *(const u64*)&S[(row + i) * SPAD + ch * 64 + c]; // broadcast pair
                u64 plo = splat2(flo(pp));
                u64 phi = splat2(fhi(pp));
                ffma2(accd[i][0], plo, vlo.d[0]);
                ffma2(accd[i][1], plo, vlo.d[1]);
                ffma2(accd[i][0], phi, vhi.d[0]);
                ffma2(accd[i][1], phi, vhi.d[1]);
            }
        }
    }

    // ---- normalize + store (float4, coalesced) ----
    #pragma unroll
    for (int i = 0; i < 4; i++) {
        float inv = rinv[row + i];
        float4 o;
        o.x = flo(accd[i][0]) * inv;
        o.y = fhi(accd[i][0]) * inv;
        o.z = flo(accd[i][1]) * inv;
        o.w = fhi(accd[i][1]) * inv;
        *(float4*)&og[(size_t)(i0 + row + i) * DMODEL + hoff + 4 * tx] = o;
    }
}

extern "C" void kernel_launch(void* const* d_in, const int* in_sizes, int n_in,
                              void* d_out, int out_size) {
    (void)in_sizes; (void)n_in; (void)out_size;
    const float* q = (const float*)d_in[0];
    const float* k = (const float*)d_in[1];
    const float* v = (const float*)d_in[2];
    float* o = (float*)d_out;

    cudaFuncSetAttribute(sparse_attn_kernel,
                         cudaFuncAttributeMaxDynamicSharedMemorySize, SMEM_BYTES);
    dim3 grid(NSEQ / QT, HEADS);
    sparse_attn_kernel<<<grid, 256, SMEM_BYTES>>>(q, k, v, o);
}

// round 3
// speedup vs baseline: 1.6180x; 1.6180x over previous
#include <cuda_runtime.h>
#include <math.h>

#define NSEQ   2048
#define DMODEL 1024
#define HEADS  16
#define DH     64
#define CTX    128
#define QT     64        // queries per block
#define NCHUNK 5
#define KVP    68        // padded K/V/P chunk row stride (floats)
#define SCALE  0.125f    // 1/sqrt(64)

#define SMEM_FLOATS (QT*DH + 3*64*KVP)
#define SMEM_BYTES  (SMEM_FLOATS * 4)

typedef unsigned long long u64;

union F4 { float4 f; u64 d[2]; };

// packed f32x2 ops
__device__ __forceinline__ void ffma2(u64& acc, u64 a, u64 b) {
    asm("fma.rn.f32x2 %0, %1, %2, %0;" : "+l"(acc) : "l"(a), "l"(b));
}
__device__ __forceinline__ u64 mul2(u64 a, u64 b) {
    u64 r; asm("mul.rn.f32x2 %0, %1, %2;" : "=l"(r) : "l"(a), "l"(b));
    return r;
}
__device__ __forceinline__ u64 splat2(float x) {
    u64 r; unsigned u = __float_as_uint(x);
    asm("mov.b64 %0, {%1, %1};" : "=l"(r) : "r"(u));
    return r;
}
__device__ __forceinline__ float flo(u64 d) { return __uint_as_float((unsigned)d); }
__device__ __forceinline__ float fhi(u64 d) { return __uint_as_float((unsigned)(d >> 32)); }

// exp(x) for x <= 0 via FMA-pipe polynomial (avoids the MUFU wall). ~3e-6 rel err.
__device__ __forceinline__ float fastexp(float x) {
    x = fmaxf(x, -80.0f);
    float y  = x * 1.4426950408889634f;
    float t  = y + 12582912.0f;
    float fn = t - 12582912.0f;
    float f  = y - fn;
    int   n  = (int)fn;
    float p  = 1.3333558146e-3f;
    p = fmaf(p, f, 9.6181291076e-3f);
    p = fmaf(p, f, 5.5504108664e-2f);
    p = fmaf(p, f, 2.4022650696e-1f);
    p = fmaf(p, f, 6.9314718056e-1f);
    p = fmaf(p, f, 1.0f);
    return p * __int_as_float((n + 127) << 23);
}

__global__ void __launch_bounds__(256, 2)
sparse_attn_kernel(const float* __restrict__ qg, const float* __restrict__ kg,
                   const float* __restrict__ vg, float* __restrict__ og)
{
    extern __shared__ float sm[];
    float* Qs = sm;                 // [64][64]   16 KB
    float* Ks = Qs + QT * DH;       // [64][KVP]  17 KB (XOR-swizzled rows)
    float* Vs = Ks + 64 * KVP;      // [64][KVP]  17 KB
    float* Ps = Vs + 64 * KVP;      // [64][KVP]  17 KB (probabilities, this chunk)

    const int h  = blockIdx.y;
    const int i0 = blockIdx.x * QT;
    const int t  = threadIdx.x;
    const int tx = t & 15, ty = t >> 4;
    const int row = ty * 4;                 // this thread's 4 query rows
    const int ksw = ((tx >> 3) & 1) * 16;   // K-tile read swizzle selector
    const size_t hoff = (size_t)h * DH;

    // ---- load Q tile (coalesced) ----
    for (int idx = t; idx < QT * DH; idx += 256) {
        int r = idx >> 6, c = idx & 63;
        Qs[idx] = qg[(size_t)(i0 + r) * DMODEL + hoff + c];
    }

    // online softmax state (replicated across the 16 tx threads of each row)
    float m[4], l[4];
    u64 accd[4][2];
    #pragma unroll
    for (int i = 0; i < 4; i++) {
        m[i] = -1e30f; l[i] = 0.f; accd[i][0] = 0ull; accd[i][1] = 0ull;
    }

    for (int ch = 0; ch < NCHUNK; ch++) {
        const int jc = i0 - CTX + ch * 64;
        const bool valid = (jc + 63 >= 0) && (jc < NSEQ);   // block-uniform
        __syncthreads();                                     // K/V/P buffer reuse fence
        if (valid) {
            for (int idx = t; idx < 64 * 16; idx += 256) {
                int r = idx >> 4, c4 = (idx & 15) * 4;
                int j = jc + r;
                float4 kval = make_float4(0.f, 0.f, 0.f, 0.f);
                float4 vval = kval;
                if (j >= 0 && j < NSEQ) {
                    kval = *(const float4*)&kg[(size_t)j * DMODEL + hoff + c4];
                    vval = *(const float4*)&vg[(size_t)j * DMODEL + hoff + c4];
                }
                *(float4*)&Ks[r * KVP + (c4 ^ (((r >> 3) & 1) * 16))] = kval;
                *(float4*)&Vs[r * KVP + c4] = vval;
            }
        }
        __syncthreads();
        if (valid) {
            // ---- QK -> acc[4][4] ----
            u64 acc[4][4];
            #pragma unroll
            for (int i = 0; i < 4; i++)
                #pragma unroll
                for (int j = 0; j < 4; j++) acc[i][j] = 0ull;

            #pragma unroll
            for (int kk = 0; kk < DH; kk += 4) {
                F4 qv[4], kv[4];
                #pragma unroll
                for (int i = 0; i < 4; i++)
                    qv[i].f = *(const float4*)&Qs[(row + i) * DH + kk];   // broadcast
                #pragma unroll
                for (int j = 0; j < 4; j++)
                    kv[j].f = *(const float4*)&Ks[(tx + 16 * j) * KVP + (kk ^ ksw)]; // conflict-free
                #pragma unroll
                for (int i = 0; i < 4; i++)
                    #pragma unroll
                    for (int j = 0; j < 4; j++) {
                        ffma2(acc[i][j], qv[i].d[0], kv[j].d[0]);
                        ffma2(acc[i][j], qv[i].d[1], kv[j].d[1]);
                    }
            }

            // ---- online softmax update, write P chunk ----
            #pragma unroll
            for (int i = 0; i < 4; i++) {
                const int ig = i0 + row + i;
                float s[4];
                float mc = -1e30f;
                #pragma unroll
                for (int j = 0; j < 4; j++) {
                    int jg = jc + tx + 16 * j;
                    float v = (flo(acc[i][j]) + fhi(acc[i][j])) * SCALE;
                    if (jg < 0 || jg >= NSEQ || abs(ig - jg) > CTX) v = -1e30f;
                    s[j] = v;
                    mc = fmaxf(mc, v);
                }
                #pragma unroll
                for (int o = 8; o > 0; o >>= 1)   // reduce across 16 tx lanes
                    mc = fmaxf(mc, __shfl_xor_sync(0xffffffffu, mc, o));
                float mnew  = fmaxf(m[i], mc);
                float alpha = fastexp(m[i] - mnew);
                m[i] = mnew;
                u64 a2 = splat2(alpha);
                accd[i][0] = mul2(accd[i][0], a2);
                accd[i][1] = mul2(accd[i][1], a2);
                float psum = 0.f;
                #pragma unroll
                for (int j = 0; j < 4; j++) {
                    float p = fastexp(s[j] - mnew);   // masked -> e^-80 ~= 0
                    psum += p;
                    Ps[(row + i) * KVP + tx + 16 * j] = p;
                }
                l[i] = l[i] * alpha + psum;
            }
        }
        __syncthreads();
        if (valid) {
            // ---- PV accumulate from this chunk ----
            #pragma unroll 4
            for (int c = 0; c < 64; c += 2) {
                F4 vlo, vhi;
                vlo.f = *(const float4*)&Vs[c * KVP + 4 * tx];
                vhi.f = *(const float4*)&Vs[(c + 1) * KVP + 4 * tx];
                #pragma unroll
                for (int i = 0; i < 4; i++) {
                    u64 pp  = *(const u64*)&Ps[(row + i) * KVP + c]; // broadcast pair
                    u64 plo = splat2(flo(pp));
                    u64 phi = splat2(fhi(pp));
                    ffma2(accd[i][0], plo, vlo.d[0]);
                    ffma2(accd[i][1], plo, vlo.d[1]);
                    ffma2(accd[i][0], phi, vhi.d[0]);
                    ffma2(accd[i][1], phi, vhi.d[1]);
                }
            }
        }
    }

    // ---- finalize: reduce l across tx lanes, normalize, store ----
    #pragma unroll
    for (int i = 0; i < 4; i++) {
        float ls = l[i];
        #pragma unroll
        for (int o = 8; o > 0; o >>= 1)
            ls += __shfl_xor_sync(0xffffffffu, ls, o);
        float inv = 1.0f / ls;
        float4 o4;
        o4.x = flo(accd[i][0]) * inv;
        o4.y = fhi(accd[i][0]) * inv;
        o4.z = flo(accd[i][1]) * inv;
        o4.w = fhi(accd[i][1]) * inv;
        *(float4*)&og[(size_t)(i0 + row + i) * DMODEL + hoff + 4 * tx] = o4;
    }
}

extern "C" void kernel_launch(void* const* d_in, const int* in_sizes, int n_in,
                              void* d_out, int out_size) {
    (void)in_sizes; (void)n_in; (void)out_size;
    const float* q = (const float*)d_in[0];
    const float* k = (const float*)d_in[1];
    const float* v = (const float*)d_in[2];
    float* o = (float*)d_out;

    cudaFuncSetAttribute(sparse_attn_kernel,
                         cudaFuncAttributeMaxDynamicSharedMemorySize, SMEM_BYTES);
    dim3 grid(NSEQ / QT, HEADS);
    sparse_attn_kernel<<<grid, 256, SMEM_BYTES>>>(q, k, v, o);
}

// round 5
// speedup vs baseline: 3.2412x; 2.0033x over previous
#include <cuda_runtime.h>
#include <cuda_bf16.h>
#include <cstdint>

#define NSEQ   2048
#define DMODEL 1024
#define HEADS  16
#define DH     64
#define CTX    128
#define QT     64
#define NCHUNK 5
#define SP     72            // padded smem row stride (bf16 elems) -> 144B
#define SCALE  0.125f

// ---- smem byte offsets ----
#define QHI 0
#define QLO (QHI + 64*SP*2)
#define KHI (QLO + 64*SP*2)
#define KLO (KHI + 64*SP*2)
#define VHI (KLO + 64*SP*2)
#define VLO (VHI + 64*SP*2)
#define LSM (VLO + 64*SP*2)          // 128 floats: per-wc row sums
#define SMEM_BYTES (LSM + 128*4)
#define OPART QHI                    // epilogue reuse: 64x64 f32 partials
#define OBUF  KHI                    // epilogue reuse: 64x68 f32 staging

__device__ __forceinline__ uint32_t smem_u32(const void* p) {
    uint32_t a;
    asm("{ .reg .u64 t; cvta.to.shared.u64 t, %1; cvt.u32.u64 %0, t; }" : "=r"(a) : "l"(p));
    return a;
}
__device__ __forceinline__ void ldsm4(uint32_t* r, uint32_t a) {
    asm volatile("ldmatrix.sync.aligned.m8n8.x4.shared.b16 {%0,%1,%2,%3}, [%4];"
                 : "=r"(r[0]), "=r"(r[1]), "=r"(r[2]), "=r"(r[3]) : "r"(a));
}
__device__ __forceinline__ void ldsm4t(uint32_t* r, uint32_t a) {
    asm volatile("ldmatrix.sync.aligned.m8n8.x4.trans.shared.b16 {%0,%1,%2,%3}, [%4];"
                 : "=r"(r[0]), "=r"(r[1]), "=r"(r[2]), "=r"(r[3]) : "r"(a));
}
__device__ __forceinline__ void mma16816(float* c, const uint32_t* a, const uint32_t* b) {
    asm volatile("mma.sync.aligned.m16n8k16.row.col.f32.bf16.bf16.f32 "
                 "{%0,%1,%2,%3}, {%4,%5,%6,%7}, {%8,%9}, {%0,%1,%2,%3};"
                 : "+f"(c[0]), "+f"(c[1]), "+f"(c[2]), "+f"(c[3])
                 : "r"(a[0]), "r"(a[1]), "r"(a[2]), "r"(a[3]), "r"(b[0]), "r"(b[1]));
}
// pack two fp32 -> bf16x2 (lo in low half)
__device__ __forceinline__ uint32_t pack_bf16(float lo, float hi) {
    uint32_t r;
    asm("cvt.rn.bf16x2.f32 %0, %1, %2;" : "=r"(r) : "f"(hi), "f"(lo));
    return r;
}
__device__ __forceinline__ float bf16_hi(float x) {
    return __bfloat162float(__float2bfloat16(x));
}
// exp on the FMA pipe (inputs in [-80, ~6]); ~3e-6 rel err
__device__ __forceinline__ float fastexp(float x) {
    x = fmaxf(x, -80.0f);
    float y  = x * 1.4426950408889634f;
    float t  = y + 12582912.0f;
    float fn = t - 12582912.0f;
    float f  = y - fn;
    int   n  = (int)fn;
    float p  = 1.3333558146e-3f;
    p = fmaf(p, f, 9.6181291076e-3f);
    p = fmaf(p, f, 5.5504108664e-2f);
    p = fmaf(p, f, 2.4022650696e-1f);
    p = fmaf(p, f, 6.9314718056e-1f);
    p = fmaf(p, f, 1.0f);
    return p * __int_as_float((n + 127) << 23);
}

__global__ void __launch_bounds__(256, 2)
sparse_attn_mma(const float* __restrict__ qg, const float* __restrict__ kg,
                const float* __restrict__ vg, float* __restrict__ og)
{
    extern __shared__ char smem[];
    const uint32_t sb = smem_u32(smem);
    const int t    = threadIdx.x;
    const int lane = t & 31, wid = t >> 5;
    const int wr   = wid & 3;          // row group: 16 rows
    const int wc   = wid >> 2;         // col group: 32 keys
    const int g    = lane >> 2;        // row-in-group (and +8)
    const int qa   = lane & 3;         // col pair selector
    const int h    = blockIdx.y;
    const int i0   = blockIdx.x * QT;
    const size_t hoff = (size_t)h * DH;

    // ---- load Q once: scale, split hi/lo bf16 ----
    for (int idx = t; idx < 64 * 16; idx += 256) {
        int r = idx >> 4, c4 = (idx & 15) * 4;
        float4 q4 = *(const float4*)&qg[(size_t)(i0 + r) * DMODEL + hoff + c4];
        q4.x *= SCALE; q4.y *= SCALE; q4.z *= SCALE; q4.w *= SCALE;
        float hx = bf16_hi(q4.x), hy = bf16_hi(q4.y), hz = bf16_hi(q4.z), hw = bf16_hi(q4.w);
        uint32_t boff = (uint32_t)(r * SP + c4) * 2;
        *(uint2*)(smem + QHI + boff) = make_uint2(pack_bf16(hx, hy), pack_bf16(hz, hw));
        *(uint2*)(smem + QLO + boff) = make_uint2(pack_bf16(q4.x - hx, q4.y - hy),
                                                  pack_bf16(q4.z - hz, q4.w - hw));
    }

    // ldmatrix per-lane byte offsets
    const int l = lane;
    const uint32_t aoffA = (uint32_t)(((wr * 16 + (l & 15)) * SP + (l >> 4) * 8) * 2);
    const uint32_t aoffB = (uint32_t)(((wc * 32 + (l & 7) + ((l >> 4) & 1) * 8) * SP
                                      + ((l >> 3) & 1) * 8) * 2);
    const uint32_t aoffV = (uint32_t)(((wc * 32 + (l & 7) + ((l >> 3) & 1) * 8) * SP
                                      + ((l >> 4) & 1) * 8) * 2);

    float oacc[8][4];
    #pragma unroll
    for (int i = 0; i < 8; i++)
        #pragma unroll
        for (int j = 0; j < 4; j++) oacc[i][j] = 0.f;
    float l0 = 0.f, l1 = 0.f;

    const int ig0 = i0 + wr * 16 + g, ig1 = ig0 + 8;

    for (int ch = 0; ch < NCHUNK; ch++) {
        const int jc = i0 - CTX + ch * 64;
        if (jc < 0 || jc >= NSEQ) continue;   // chunks are never partial

        __syncthreads();   // protect K/V (and Q on first iter) from prior readers
        for (int idx = t; idx < 64 * 16; idx += 256) {
            int r = idx >> 4, c4 = (idx & 15) * 4;
            uint32_t boff = (uint32_t)(r * SP + c4) * 2;
            float4 k4 = *(const float4*)&kg[(size_t)(jc + r) * DMODEL + hoff + c4];
            float hx = bf16_hi(k4.x), hy = bf16_hi(k4.y), hz = bf16_hi(k4.z), hw = bf16_hi(k4.w);
            *(uint2*)(smem + KHI + boff) = make_uint2(pack_bf16(hx, hy), pack_bf16(hz, hw));
            *(uint2*)(smem + KLO + boff) = make_uint2(pack_bf16(k4.x - hx, k4.y - hy),
                                                      pack_bf16(k4.z - hz, k4.w - hw));
            float4 v4 = *(const float4*)&vg[(size_t)(jc + r) * DMODEL + hoff + c4];
            hx = bf16_hi(v4.x); hy = bf16_hi(v4.y); hz = bf16_hi(v4.z); hw = bf16_hi(v4.w);
            *(uint2*)(smem + VHI + boff) = make_uint2(pack_bf16(hx, hy), pack_bf16(hz, hw));
            *(uint2*)(smem + VLO + boff) = make_uint2(pack_bf16(v4.x - hx, v4.y - hy),
                                                      pack_bf16(v4.z - hz, v4.w - hw));
        }
        __syncthreads();

        // ---- GEMM1: S = Q K^T, bf16 x3 ----
        float sacc[4][4];
        #pragma unroll
        for (int i = 0; i < 4; i++)
            #pragma unroll
            for (int j = 0; j < 4; j++) sacc[i][j] = 0.f;

        #pragma unroll
        for (int k = 0; k < 4; k++) {
            uint32_t ah[4], al[4];
            ldsm4(ah, sb + QHI + aoffA + k * 32);
            ldsm4(al, sb + QLO + aoffA + k * 32);
            #pragma unroll
            for (int nt2 = 0; nt2 < 2; nt2++) {
                uint32_t bh[4], bl[4];
                ldsm4(bh, sb + KHI + aoffB + nt2 * (16 * SP * 2) + k * 32);
                ldsm4(bl, sb + KLO + aoffB + nt2 * (16 * SP * 2) + k * 32);
                mma16816(sacc[2 * nt2],     ah, bh);
                mma16816(sacc[2 * nt2],     ah, bl);
                mma16816(sacc[2 * nt2],     al, bh);
                mma16816(sacc[2 * nt2 + 1], ah, bh + 2);
                mma16816(sacc[2 * nt2 + 1], ah, bl + 2);
                mma16816(sacc[2 * nt2 + 1], al, bh + 2);
            }
        }

        // ---- softmax (unnormalized exp; band mask -> exact 0) + P fragments ----
        uint32_t pah[2][4], pal[2][4];
        #pragma unroll
        for (int nt = 0; nt < 4; nt++) {
            int jg0 = jc + wc * 32 + nt * 8 + 2 * qa, jg1 = jg0 + 1;
            float p00 = (abs(ig0 - jg0) <= CTX) ? fastexp(sacc[nt][0]) : 0.f;
            float p01 = (abs(ig0 - jg1) <= CTX) ? fastexp(sacc[nt][1]) : 0.f;
            float p10 = (abs(ig1 - jg0) <= CTX) ? fastexp(sacc[nt][2]) : 0.f;
            float p11 = (abs(ig1 - jg1) <= CTX) ? fastexp(sacc[nt][3]) : 0.f;
            l0 += p00 + p01; l1 += p10 + p11;
            float h00 = bf16_hi(p00), h01 = bf16_hi(p01);
            float h10 = bf16_hi(p10), h11 = bf16_hi(p11);
            pah[nt >> 1][(nt & 1) * 2 + 0] = pack_bf16(h00, h01);
            pah[nt >> 1][(nt & 1) * 2 + 1] = pack_bf16(h10, h11);
            pal[nt >> 1][(nt & 1) * 2 + 0] = pack_bf16(p00 - h00, p01 - h01);
            pal[nt >> 1][(nt & 1) * 2 + 1] = pack_bf16(p10 - h10, p11 - h11);
        }

        // ---- GEMM2: O += P V, bf16 x3 (V frags via ldmatrix.trans) ----
        #pragma unroll
        for (int ks = 0; ks < 2; ks++) {
            #pragma unroll
            for (int nt2 = 0; nt2 < 4; nt2++) {
                uint32_t vh[4], vl[4];
                ldsm4t(vh, sb + VHI + aoffV + ks * (16 * SP * 2) + nt2 * 32);
                ldsm4t(vl, sb + VLO + aoffV + ks * (16 * SP * 2) + nt2 * 32);
                mma16816(oacc[2 * nt2],     pah[ks], vh);
                mma16816(oacc[2 * nt2],     pah[ks], vl);
                mma16816(oacc[2 * nt2],     pal[ks], vh);
                mma16816(oacc[2 * nt2 + 1], pah[ks], vh + 2);
                mma16816(oacc[2 * nt2 + 1], pah[ks], vl + 2);
                mma16816(oacc[2 * nt2 + 1], pal[ks], vh + 2);
            }
        }
    }

    // ---- epilogue: reduce row sums + cross-warp O reduction ----
    l0 += __shfl_xor_sync(0xffffffffu, l0, 1);
    l0 += __shfl_xor_sync(0xffffffffu, l0, 2);
    l1 += __shfl_xor_sync(0xffffffffu, l1, 1);
    l1 += __shfl_xor_sync(0xffffffffu, l1, 2);
    float* Ls = (float*)(smem + LSM);
    if (qa == 0) {
        Ls[wc * 64 + wr * 16 + g]     = l0;
        Ls[wc * 64 + wr * 16 + g + 8] = l1;
    }
    __syncthreads();   // all MMA/ldmatrix reads done; safe to reuse smem

    float* Op = (float*)(smem + OPART);
    const int r0 = wr * 16 + g, r1 = r0 + 8;
    if (wc == 1) {
        #pragma unroll
        for (int nt = 0; nt < 8; nt++) {
            int c = nt * 8 + 2 * qa;
            *(float2*)&Op[r0 * 64 + c] = make_float2(oacc[nt][0], oacc[nt][1]);
            *(float2*)&Op[r1 * 64 + c] = make_float2(oacc[nt][2], oacc[nt][3]);
        }
    }
    __syncthreads();

    float* Ob = (float*)(smem + OBUF);
    if (wc == 0) {
        float inv0 = 1.0f / (Ls[r0] + Ls[64 + r0]);
        float inv1 = 1.0f / (Ls[r1] + Ls[64 + r1]);
        #pragma unroll
        for (int nt = 0; nt < 8; nt++) {
            int c = nt * 8 + 2 * qa;
            float2 q0 = *(float2*)&Op[r0 * 64 + c];
            float2 q1 = *(float2*)&Op[r1 * 64 + c];
            *(float2*)&Ob[r0 * 68 + c] = make_float2((oacc[nt][0] + q0.x) * inv0,
                                                     (oacc[nt][1] + q0.y) * inv0);
            *(float2*)&Ob[r1 * 68 + c] = make_float2((oacc[nt][2] + q1.x) * inv1,
                                                     (oacc[nt][3] + q1.y) * inv1);
        }
    }
    __syncthreads();

    for (int idx = t; idx < 64 * 16; idx += 256) {
        int r = idx >> 4, c4 = (idx & 15) * 4;
        float4 o4 = *(const float4*)&Ob[r * 68 + c4];
        *(float4*)&og[(size_t)(i0 + r) * DMODEL + hoff + c4] = o4;
    }
}

extern "C" void kernel_launch(void* const* d_in, const int* in_sizes, int n_in,
                              void* d_out, int out_size) {
    (void)in_sizes; (void)n_in; (void)out_size;
    const float* q = (const float*)d_in[0];
    const float* k = (const float*)d_in[1];
    const float* v = (const float*)d_in[2];
    float* o = (float*)d_out;

    cudaFuncSetAttribute(sparse_attn_mma,
                         cudaFuncAttributeMaxDynamicSharedMemorySize, SMEM_BYTES);
    dim3 grid(NSEQ / QT, HEADS);
    sparse_attn_mma<<<grid, 256, SMEM_BYTES>>>(q, k, v, o);
}

// round 6
// speedup vs baseline: 3.3865x; 1.0448x over previous
#include <cuda_runtime.h>
#include <cuda_bf16.h>
#include <cstdint>

#define NSEQ   2048
#define DMODEL 1024
#define HEADS  16
#define DH     64
#define CTX    128
#define QT     64
#define NCHUNK 5
#define SP     72            // padded smem row stride (bf16 elems) -> 144B
#define SCALE  0.125f

// ---- smem byte offsets ----
#define QHI 0
#define QLO (QHI + 64*SP*2)
#define KHI (QLO + 64*SP*2)
#define KLO (KHI + 64*SP*2)
#define VHI (KLO + 64*SP*2)
#define VLO (VHI + 64*SP*2)
#define LSM (VLO + 64*SP*2)          // 128 floats: per-wc row sums
#define RAWK (LSM + 512)             // fp32 staging 64x64
#define RAWV (RAWK + 16384)
#define SMEM_BYTES (RAWV + 16384)
#define OPART QHI                    // epilogue reuse: 64x64 f32 partials
#define OBUF  KHI                    // epilogue reuse: 64x68 f32 staging

__device__ __forceinline__ uint32_t smem_u32(const void* p) {
    uint32_t a;
    asm("{ .reg .u64 t; cvta.to.shared.u64 t, %1; cvt.u32.u64 %0, t; }" : "=r"(a) : "l"(p));
    return a;
}
__device__ __forceinline__ void cpa16(uint32_t dst, const void* src) {
    asm volatile("cp.async.cg.shared.global [%0], [%1], 16;" :: "r"(dst), "l"(src));
}
#define CPA_COMMIT() asm volatile("cp.async.commit_group;" ::: "memory")
#define CPA_WAIT0()  asm volatile("cp.async.wait_group 0;" ::: "memory")

__device__ __forceinline__ void ldsm4(uint32_t* r, uint32_t a) {
    asm volatile("ldmatrix.sync.aligned.m8n8.x4.shared.b16 {%0,%1,%2,%3}, [%4];"
                 : "=r"(r[0]), "=r"(r[1]), "=r"(r[2]), "=r"(r[3]) : "r"(a));
}
__device__ __forceinline__ void ldsm4t(uint32_t* r, uint32_t a) {
    asm volatile("ldmatrix.sync.aligned.m8n8.x4.trans.shared.b16 {%0,%1,%2,%3}, [%4];"
                 : "=r"(r[0]), "=r"(r[1]), "=r"(r[2]), "=r"(r[3]) : "r"(a));
}
__device__ __forceinline__ void mma16816(float* c, const uint32_t* a, const uint32_t* b) {
    asm volatile("mma.sync.aligned.m16n8k16.row.col.f32.bf16.bf16.f32 "
                 "{%0,%1,%2,%3}, {%4,%5,%6,%7}, {%8,%9}, {%0,%1,%2,%3};"
                 : "+f"(c[0]), "+f"(c[1]), "+f"(c[2]), "+f"(c[3])
                 : "r"(a[0]), "r"(a[1]), "r"(a[2]), "r"(a[3]), "r"(b[0]), "r"(b[1]));
}
__device__ __forceinline__ uint32_t pack_bf16(float lo, float hi) {
    uint32_t r;
    asm("cvt.rn.bf16x2.f32 %0, %1, %2;" : "=r"(r) : "f"(hi), "f"(lo));
    return r;
}
__device__ __forceinline__ float bf16_hi(float x) {
    return __bfloat162float(__float2bfloat16(x));
}
// exp on the FMA pipe (inputs in [-80, ~6]); ~3e-6 rel err
__device__ __forceinline__ float fastexp(float x) {
    x = fmaxf(x, -80.0f);
    float y  = x * 1.4426950408889634f;
    float t  = y + 12582912.0f;
    float fn = t - 12582912.0f;
    float f  = y - fn;
    int   n  = (int)fn;
    float p  = 1.3333558146e-3f;
    p = fmaf(p, f, 9.6181291076e-3f);
    p = fmaf(p, f, 5.5504108664e-2f);
    p = fmaf(p, f, 2.4022650696e-1f);
    p = fmaf(p, f, 6.9314718056e-1f);
    p = fmaf(p, f, 1.0f);
    return p * __int_as_float((n + 127) << 23);
}

__global__ void __launch_bounds__(256, 2)
sparse_attn_mma(const float* __restrict__ qg, const float* __restrict__ kg,
                const float* __restrict__ vg, float* __restrict__ og)
{
    extern __shared__ char smem[];
    const uint32_t sb = smem_u32(smem);
    const int t    = threadIdx.x;
    const int lane = t & 31, wid = t >> 5;
    const int wr   = wid & 3;          // row group: 16 rows
    const int wc   = wid >> 2;         // col group: 32 keys
    const int g    = lane >> 2;        // row-in-group (and +8)
    const int qa   = lane & 3;         // col pair selector
    const int h    = blockIdx.y;
    const int i0   = blockIdx.x * QT;
    const size_t hoff = (size_t)h * DH;

    // thread's staging slice coords (8 cp.async of 16B: 4 K rows + 4 V rows worth)
    const int pr = t >> 4, pc4 = (t & 15) * 4;  // strided by 16 rows per iter

    // ---- load Q once: scale, split hi/lo bf16 ----
    for (int idx = t; idx < 64 * 16; idx += 256) {
        int r = idx >> 4, c4 = (idx & 15) * 4;
        float4 q4 = *(const float4*)&qg[(size_t)(i0 + r) * DMODEL + hoff + c4];
        q4.x *= SCALE; q4.y *= SCALE; q4.z *= SCALE; q4.w *= SCALE;
        float hx = bf16_hi(q4.x), hy = bf16_hi(q4.y), hz = bf16_hi(q4.z), hw = bf16_hi(q4.w);
        uint32_t boff = (uint32_t)(r * SP + c4) * 2;
        *(uint2*)(smem + QHI + boff) = make_uint2(pack_bf16(hx, hy), pack_bf16(hz, hw));
        *(uint2*)(smem + QLO + boff) = make_uint2(pack_bf16(q4.x - hx, q4.y - hy),
                                                  pack_bf16(q4.z - hz, q4.w - hw));
    }

    // ldmatrix per-lane byte offsets
    const int l = lane;
    const uint32_t aoffA = (uint32_t)(((wr * 16 + (l & 15)) * SP + (l >> 4) * 8) * 2);
    const uint32_t aoffB = (uint32_t)(((wc * 32 + (l & 7) + ((l >> 4) & 1) * 8) * SP
                                      + ((l >> 3) & 1) * 8) * 2);
    const uint32_t aoffV = (uint32_t)(((wc * 32 + (l & 7) + ((l >> 3) & 1) * 8) * SP
                                      + ((l >> 4) & 1) * 8) * 2);

    float oacc[8][4];
    #pragma unroll
    for (int i = 0; i < 8; i++)
        #pragma unroll
        for (int j = 0; j < 4; j++) oacc[i][j] = 0.f;
    float l0 = 0.f, l1 = 0.f;

    const int ig0 = i0 + wr * 16 + g, ig1 = ig0 + 8;

    // contiguous valid chunk range: jc in [0, NSEQ-64]
    const int chlo = (i0 >= CTX) ? 0 : (CTX - i0 + 63) / 64;
    const int chhi = min(NCHUNK - 1, (NSEQ - 64 - i0 + CTX) / 64);

    // prologue prefetch: chunk chlo
    {
        const int jc = i0 - CTX + chlo * 64;
        #pragma unroll
        for (int it = 0; it < 4; it++) {
            int r = pr + it * 16;
            const float* ks = &kg[(size_t)(jc + r) * DMODEL + hoff + pc4];
            const float* vs = &vg[(size_t)(jc + r) * DMODEL + hoff + pc4];
            cpa16(sb + RAWK + (uint32_t)(r * 64 + pc4) * 4, ks);
            cpa16(sb + RAWV + (uint32_t)(r * 64 + pc4) * 4, vs);
        }
        CPA_COMMIT();
    }

    for (int ch = chlo; ch <= chhi; ch++) {
        const int jc = i0 - CTX + ch * 64;

        CPA_WAIT0();
        __syncthreads();   // raw staged + all warps done reading split bufs of ch-1

        // ---- convert raw fp32 -> split hi/lo bf16 tiles (smem -> smem) ----
        for (int idx = t; idx < 64 * 16; idx += 256) {
            int r = idx >> 4, c4 = (idx & 15) * 4;
            uint32_t boff = (uint32_t)(r * SP + c4) * 2;
            float4 k4 = *(const float4*)(smem + RAWK + (uint32_t)(r * 64 + c4) * 4);
            float hx = bf16_hi(k4.x), hy = bf16_hi(k4.y), hz = bf16_hi(k4.z), hw = bf16_hi(k4.w);
            *(uint2*)(smem + KHI + boff) = make_uint2(pack_bf16(hx, hy), pack_bf16(hz, hw));
            *(uint2*)(smem + KLO + boff) = make_uint2(pack_bf16(k4.x - hx, k4.y - hy),
                                                      pack_bf16(k4.z - hz, k4.w - hw));
            float4 v4 = *(const float4*)(smem + RAWV + (uint32_t)(r * 64 + c4) * 4);
            hx = bf16_hi(v4.x); hy = bf16_hi(v4.y); hz = bf16_hi(v4.z); hw = bf16_hi(v4.w);
            *(uint2*)(smem + VHI + boff) = make_uint2(pack_bf16(hx, hy), pack_bf16(hz, hw));
            *(uint2*)(smem + VLO + boff) = make_uint2(pack_bf16(v4.x - hx, v4.y - hy),
                                                      pack_bf16(v4.z - hz, v4.w - hw));
        }
        __syncthreads();   // split tiles ready; raw bufs free for next prefetch

        // ---- prefetch next chunk (overlaps GEMM compute) ----
        if (ch < chhi) {
            const int jn = jc + 64;
            #pragma unroll
            for (int it = 0; it < 4; it++) {
                int r = pr + it * 16;
                const float* ks = &kg[(size_t)(jn + r) * DMODEL + hoff + pc4];
                const float* vs = &vg[(size_t)(jn + r) * DMODEL + hoff + pc4];
                cpa16(sb + RAWK + (uint32_t)(r * 64 + pc4) * 4, ks);
                cpa16(sb + RAWV + (uint32_t)(r * 64 + pc4) * 4, vs);
            }
            CPA_COMMIT();
        }

        // ---- skip warp tiles entirely outside the band (boundary chunks) ----
        const int doff = jc - i0;
        if ((doff + wc * 32 + 31 < wr * 16 - CTX) || (doff + wc * 32 > wr * 16 + 15 + CTX))
            continue;

        // ---- GEMM1: S = Q K^T, bf16 x3 ----
        float sacc[4][4];
        #pragma unroll
        for (int i = 0; i < 4; i++)
            #pragma unroll
            for (int j = 0; j < 4; j++) sacc[i][j] = 0.f;

        #pragma unroll
        for (int k = 0; k < 4; k++) {
            uint32_t ah[4], al[4];
            ldsm4(ah, sb + QHI + aoffA + k * 32);
            ldsm4(al, sb + QLO + aoffA + k * 32);
            #pragma unroll
            for (int nt2 = 0; nt2 < 2; nt2++) {
                uint32_t bh[4], bl[4];
                ldsm4(bh, sb + KHI + aoffB + nt2 * (16 * SP * 2) + k * 32);
                ldsm4(bl, sb + KLO + aoffB + nt2 * (16 * SP * 2) + k * 32);
                mma16816(sacc[2 * nt2],     ah, bh);
                mma16816(sacc[2 * nt2],     ah, bl);
                mma16816(sacc[2 * nt2],     al, bh);
                mma16816(sacc[2 * nt2 + 1], ah, bh + 2);
                mma16816(sacc[2 * nt2 + 1], ah, bl + 2);
                mma16816(sacc[2 * nt2 + 1], al, bh + 2);
            }
        }

        // ---- softmax (unnormalized exp; band mask -> exact 0) + P fragments ----
        uint32_t pah[2][4], pal[2][4];
        #pragma unroll
        for (int nt = 0; nt < 4; nt++) {
            int jg0 = jc + wc * 32 + nt * 8 + 2 * qa, jg1 = jg0 + 1;
            float p00 = (abs(ig0 - jg0) <= CTX) ? fastexp(sacc[nt][0]) : 0.f;
            float p01 = (abs(ig0 - jg1) <= CTX) ? fastexp(sacc[nt][1]) : 0.f;
            float p10 = (abs(ig1 - jg0) <= CTX) ? fastexp(sacc[nt][2]) : 0.f;
            float p11 = (abs(ig1 - jg1) <= CTX) ? fastexp(sacc[nt][3]) : 0.f;
            l0 += p00 + p01; l1 += p10 + p11;
            float h00 = bf16_hi(p00), h01 = bf16_hi(p01);
            float h10 = bf16_hi(p10), h11 = bf16_hi(p11);
            pah[nt >> 1][(nt & 1) * 2 + 0] = pack_bf16(h00, h01);
            pah[nt >> 1][(nt & 1) * 2 + 1] = pack_bf16(h10, h11);
            pal[nt >> 1][(nt & 1) * 2 + 0] = pack_bf16(p00 - h00, p01 - h01);
            pal[nt >> 1][(nt & 1) * 2 + 1] = pack_bf16(p10 - h10, p11 - h11);
        }

        // ---- GEMM2: O += P V, bf16 x3 (V frags via ldmatrix.trans) ----
        #pragma unroll
        for (int ks = 0; ks < 2; ks++) {
            #pragma unroll
            for (int nt2 = 0; nt2 < 4; nt2++) {
                uint32_t vh[4], vl[4];
                ldsm4t(vh, sb + VHI + aoffV + ks * (16 * SP * 2) + nt2 * 32);
                ldsm4t(vl, sb + VLO + aoffV + ks * (16 * SP * 2) + nt2 * 32);
                mma16816(oacc[2 * nt2],     pah[ks], vh);
                mma16816(oacc[2 * nt2],     pah[ks], vl);
                mma16816(oacc[2 * nt2],     pal[ks], vh);
                mma16816(oacc[2 * nt2 + 1], pah[ks], vh + 2);
                mma16816(oacc[2 * nt2 + 1], pah[ks], vl + 2);
                mma16816(oacc[2 * nt2 + 1], pal[ks], vh + 2);
            }
        }
    }

    // ---- epilogue: reduce row sums + cross-warp O reduction ----
    l0 += __shfl_xor_sync(0xffffffffu, l0, 1);
    l0 += __shfl_xor_sync(0xffffffffu, l0, 2);
    l1 += __shfl_xor_sync(0xffffffffu, l1, 1);
    l1 += __shfl_xor_sync(0xffffffffu, l1, 2);
    float* Ls = (float*)(smem + LSM);
    if (qa == 0) {
        Ls[wc * 64 + wr * 16 + g]     = l0;
        Ls[wc * 64 + wr * 16 + g + 8] = l1;
    }
    __syncthreads();   // all MMA/ldmatrix reads done; safe to reuse smem

    float* Op = (float*)(smem + OPART);
    const int r0 = wr * 16 + g, r1 = r0 + 8;
    if (wc == 1) {
        #pragma unroll
        for (int nt = 0; nt < 8; nt++) {
            int c = nt * 8 + 2 * qa;
            *(float2*)&Op[r0 * 64 + c] = make_float2(oacc[nt][0], oacc[nt][1]);
            *(float2*)&Op[r1 * 64 + c] = make_float2(oacc[nt][2], oacc[nt][3]);
        }
    }
    __syncthreads();

    float* Ob = (float*)(smem + OBUF);
    if (wc == 0) {
        float inv0 = 1.0f / (Ls[r0] + Ls[64 + r0]);
        float inv1 = 1.0f / (Ls[r1] + Ls[64 + r1]);
        #pragma unroll
        for (int nt = 0; nt < 8; nt++) {
            int c = nt * 8 + 2 * qa;
            float2 q0 = *(float2*)&Op[r0 * 64 + c];
            float2 q1 = *(float2*)&Op[r1 * 64 + c];
            *(float2*)&Ob[r0 * 68 + c] = make_float2((oacc[nt][0] + q0.x) * inv0,
                                                     (oacc[nt][1] + q0.y) * inv0);
            *(float2*)&Ob[r1 * 68 + c] = make_float2((oacc[nt][2] + q1.x) * inv1,
                                                     (oacc[nt][3] + q1.y) * inv1);
        }
    }
    __syncthreads();

    for (int idx = t; idx < 64 * 16; idx += 256) {
        int r = idx >> 4, c4 = (idx & 15) * 4;
        float4 o4 = *(const float4*)&Ob[r * 68 + c4];
        *(float4*)&og[(size_t)(i0 + r) * DMODEL + hoff + c4] = o4;
    }
}

extern "C" void kernel_launch(void* const* d_in, const int* in_sizes, int n_in,
                              void* d_out, int out_size) {
    (void)in_sizes; (void)n_in; (void)out_size;
    const float* q = (const float*)d_in[0];
    const float* k = (const float*)d_in[1];
    const float* v = (const float*)d_in[2];
    float* o = (float*)d_out;

    cudaFuncSetAttribute(sparse_attn_mma,
                         cudaFuncAttributeMaxDynamicSharedMemorySize, SMEM_BYTES);
    dim3 grid(NSEQ / QT, HEADS);
    sparse_attn_mma<<<grid, 256, SMEM_BYTES>>>(q, k, v, o);
}

// round 7
// speedup vs baseline: 4.5650x; 1.3480x over previous
#include <cuda_runtime.h>
#include <cuda_fp16.h>
#include <cstdint>

#define NSEQ   2048
#define DMODEL 1024
#define HEADS  16
#define DH     64
#define CTX    128
#define QT     64
#define NCHUNK 5
#define SP     72            // padded smem row stride (fp16 elems) -> 144B
#define SCALE  0.125f
#define TILE   (64*SP*2)     // 9216 B per 64x64 fp16 tile

// ---- smem byte offsets ----
#define QHI  0
#define QLO  (QHI + TILE)
#define KT0  (QLO + TILE)
#define KT1  (KT0 + TILE)
#define VT0  (KT1 + TILE)
#define VT1  (VT0 + TILE)
#define LSM  (VT0 + 2*TILE)          // 128 floats
#define RAWK (LSM + 512)             // fp32 staging 64x64
#define RAWV (RAWK + 16384)
#define SMEM_BYTES (RAWV + 16384)
#define OPART 0                      // epilogue reuse: 64x64 f32 partials (over Q tiles)
#define OBUF  KT0                    // epilogue reuse: 64x68 f32 staging

__device__ __forceinline__ uint32_t smem_u32(const void* p) {
    uint32_t a;
    asm("{ .reg .u64 t; cvta.to.shared.u64 t, %1; cvt.u32.u64 %0, t; }" : "=r"(a) : "l"(p));
    return a;
}
__device__ __forceinline__ void cpa16(uint32_t dst, const void* src) {
    asm volatile("cp.async.cg.shared.global [%0], [%1], 16;" :: "r"(dst), "l"(src));
}
#define CPA_COMMIT() asm volatile("cp.async.commit_group;" ::: "memory")
#define CPA_WAIT0()  asm volatile("cp.async.wait_group 0;" ::: "memory")

__device__ __forceinline__ void ldsm4(uint32_t* r, uint32_t a) {
    asm volatile("ldmatrix.sync.aligned.m8n8.x4.shared.b16 {%0,%1,%2,%3}, [%4];"
                 : "=r"(r[0]), "=r"(r[1]), "=r"(r[2]), "=r"(r[3]) : "r"(a));
}
__device__ __forceinline__ void ldsm4t(uint32_t* r, uint32_t a) {
    asm volatile("ldmatrix.sync.aligned.m8n8.x4.trans.shared.b16 {%0,%1,%2,%3}, [%4];"
                 : "=r"(r[0]), "=r"(r[1]), "=r"(r[2]), "=r"(r[3]) : "r"(a));
}
__device__ __forceinline__ void mma16816(float* c, const uint32_t* a, const uint32_t* b) {
    asm volatile("mma.sync.aligned.m16n8k16.row.col.f32.f16.f16.f32 "
                 "{%0,%1,%2,%3}, {%4,%5,%6,%7}, {%8,%9}, {%0,%1,%2,%3};"
                 : "+f"(c[0]), "+f"(c[1]), "+f"(c[2]), "+f"(c[3])
                 : "r"(a[0]), "r"(a[1]), "r"(a[2]), "r"(a[3]), "r"(b[0]), "r"(b[1]));
}
// pack two fp32 -> fp16x2 (first arg lands in low half)
__device__ __forceinline__ uint32_t pack_f16(float lo, float hi) {
    uint32_t r;
    asm("cvt.rn.f16x2.f32 %0, %1, %2;" : "=r"(r) : "f"(hi), "f"(lo));
    return r;
}
__device__ __forceinline__ float f16_hi(float x) {
    return __half2float(__float2half_rn(x));
}
// exp on the FMA pipe (inputs in [-80, ~6]); ~3e-6 rel err
__device__ __forceinline__ float fastexp(float x) {
    x = fmaxf(x, -80.0f);
    float y  = x * 1.4426950408889634f;
    float t  = y + 12582912.0f;
    float fn = t - 12582912.0f;
    float f  = y - fn;
    int   n  = (int)fn;
    float p  = 1.3333558146e-3f;
    p = fmaf(p, f, 9.6181291076e-3f);
    p = fmaf(p, f, 5.5504108664e-2f);
    p = fmaf(p, f, 2.4022650696e-1f);
    p = fmaf(p, f, 6.9314718056e-1f);
    p = fmaf(p, f, 1.0f);
    return p * __int_as_float((n + 127) << 23);
}

__global__ void __launch_bounds__(256, 2)
sparse_attn_mma(const float* __restrict__ qg, const float* __restrict__ kg,
                const float* __restrict__ vg, float* __restrict__ og)
{
    extern __shared__ char smem[];
    const uint32_t sb = smem_u32(smem);
    const int t    = threadIdx.x;
    const int lane = t & 31, wid = t >> 5;
    const int wr   = wid & 3;          // row group: 16 rows
    const int wc   = wid >> 2;         // col group: 32 keys
    const int g    = lane >> 2;        // row-in-group (and +8)
    const int qa   = lane & 3;         // col pair selector
    const int h    = blockIdx.y;
    const int i0   = blockIdx.x * QT;
    const size_t hoff = (size_t)h * DH;

    // per-thread staging coords: each thread converts EXACTLY the bytes it
    // cp.async'd itself -> convert needs only wait_group 0, no barrier.
    const int pr = t >> 4, pc4 = (t & 15) * 4;

    // contiguous valid chunk range: jc in [0, NSEQ-64]
    const int chlo = (i0 >= CTX) ? 0 : (CTX - i0 + 63) / 64;
    const int chhi = min(NCHUNK - 1, (NSEQ - 64 - i0 + CTX) / 64);

    // ---- prologue: prefetch first chunk ----
    {
        const int jc = i0 - CTX + chlo * 64;
        #pragma unroll
        for (int it = 0; it < 4; it++) {
            int r = pr + it * 16;
            cpa16(sb + RAWK + (uint32_t)(r * 64 + pc4) * 4,
                  &kg[(size_t)(jc + r) * DMODEL + hoff + pc4]);
            cpa16(sb + RAWV + (uint32_t)(r * 64 + pc4) * 4,
                  &vg[(size_t)(jc + r) * DMODEL + hoff + pc4]);
        }
        CPA_COMMIT();
    }

    // ---- load Q once: scale, split hi/lo fp16 ----
    for (int idx = t; idx < 64 * 16; idx += 256) {
        int r = idx >> 4, c4 = (idx & 15) * 4;
        float4 q4 = *(const float4*)&qg[(size_t)(i0 + r) * DMODEL + hoff + c4];
        q4.x *= SCALE; q4.y *= SCALE; q4.z *= SCALE; q4.w *= SCALE;
        float hx = f16_hi(q4.x), hy = f16_hi(q4.y), hz = f16_hi(q4.z), hw = f16_hi(q4.w);
        uint32_t boff = (uint32_t)(r * SP + c4) * 2;
        *(uint2*)(smem + QHI + boff) = make_uint2(pack_f16(hx, hy), pack_f16(hz, hw));
        *(uint2*)(smem + QLO + boff) = make_uint2(pack_f16(q4.x - hx, q4.y - hy),
                                                  pack_f16(q4.z - hz, q4.w - hw));
    }

    // ---- prologue convert: raw -> fp16 tiles (own bytes only) ----
    {
        CPA_WAIT0();
        const uint32_t kt = KT0 + (uint32_t)(chlo & 1) * TILE;
        const uint32_t vt = VT0 + (uint32_t)(chlo & 1) * TILE;
        #pragma unroll
        for (int it = 0; it < 4; it++) {
            int r = pr + it * 16;
            uint32_t roff = (uint32_t)(r * 64 + pc4) * 4;
            uint32_t boff = (uint32_t)(r * SP + pc4) * 2;
            float4 k4 = *(const float4*)(smem + RAWK + roff);
            *(uint2*)(smem + kt + boff) = make_uint2(pack_f16(k4.x, k4.y), pack_f16(k4.z, k4.w));
            float4 v4 = *(const float4*)(smem + RAWV + roff);
            *(uint2*)(smem + vt + boff) = make_uint2(pack_f16(v4.x, v4.y), pack_f16(v4.z, v4.w));
        }
    }

    // ldmatrix per-lane byte offsets
    const int l = lane;
    const uint32_t aoffA = (uint32_t)(((wr * 16 + (l & 15)) * SP + (l >> 4) * 8) * 2);
    const uint32_t aoffB = (uint32_t)(((wc * 32 + (l & 7) + ((l >> 4) & 1) * 8) * SP
                                      + ((l >> 3) & 1) * 8) * 2);
    const uint32_t aoffV = (uint32_t)(((wc * 32 + (l & 7) + ((l >> 3) & 1) * 8) * SP
                                      + ((l >> 4) & 1) * 8) * 2);

    float oacc[8][4];
    #pragma unroll
    for (int i = 0; i < 8; i++)
        #pragma unroll
        for (int j = 0; j < 4; j++) oacc[i][j] = 0.f;
    float l0 = 0.f, l1 = 0.f;

    const int ig0 = i0 + wr * 16 + g, ig1 = ig0 + 8;

    for (int ch = chlo; ch <= chhi; ch++) {
        const int b  = ch & 1;
        const int jc = i0 - CTX + ch * 64;

        __syncthreads();   // converts(ch) visible; all reads of tiles(b) from ch-2 done

        // ---- prefetch chunk ch+1 into raw staging (overlaps compute) ----
        if (ch < chhi) {
            const int jn = jc + 64;
            #pragma unroll
            for (int it = 0; it < 4; it++) {
                int r = pr + it * 16;
                cpa16(sb + RAWK + (uint32_t)(r * 64 + pc4) * 4,
                      &kg[(size_t)(jn + r) * DMODEL + hoff + pc4]);
                cpa16(sb + RAWV + (uint32_t)(r * 64 + pc4) * 4,
                      &vg[(size_t)(jn + r) * DMODEL + hoff + pc4]);
            }
            CPA_COMMIT();
        }

        // ---- skip warp tiles entirely outside the band (boundary chunks) ----
        const int doff = jc - i0;
        const bool active = !((doff + wc * 32 + 31 < wr * 16 - CTX) ||
                              (doff + wc * 32 > wr * 16 + 15 + CTX));
        if (active) {
            const uint32_t ktb = sb + KT0 + (uint32_t)b * TILE;
            const uint32_t vtb = sb + VT0 + (uint32_t)b * TILE;

            // ---- GEMM1: S = Q K^T (Q split x2, K single fp16) ----
            float sacc[4][4];
            #pragma unroll
            for (int i = 0; i < 4; i++)
                #pragma unroll
                for (int j = 0; j < 4; j++) sacc[i][j] = 0.f;

            #pragma unroll
            for (int k = 0; k < 4; k++) {
                uint32_t ah[4], al[4];
                ldsm4(ah, sb + QHI + aoffA + k * 32);
                ldsm4(al, sb + QLO + aoffA + k * 32);
                #pragma unroll
                for (int nt2 = 0; nt2 < 2; nt2++) {
                    uint32_t bh[4];
                    ldsm4(bh, ktb + aoffB + nt2 * (16 * SP * 2) + k * 32);
                    mma16816(sacc[2 * nt2],     ah, bh);
                    mma16816(sacc[2 * nt2],     al, bh);
                    mma16816(sacc[2 * nt2 + 1], ah, bh + 2);
                    mma16816(sacc[2 * nt2 + 1], al, bh + 2);
                }
            }

            // ---- softmax (unnormalized exp; band mask -> exact 0) + P frags (split) ----
            uint32_t pah[2][4], pal[2][4];
            #pragma unroll
            for (int nt = 0; nt < 4; nt++) {
                int jg0 = jc + wc * 32 + nt * 8 + 2 * qa, jg1 = jg0 + 1;
                float p00 = (abs(ig0 - jg0) <= CTX) ? fastexp(sacc[nt][0]) : 0.f;
                float p01 = (abs(ig0 - jg1) <= CTX) ? fastexp(sacc[nt][1]) : 0.f;
                float p10 = (abs(ig1 - jg0) <= CTX) ? fastexp(sacc[nt][2]) : 0.f;
                float p11 = (abs(ig1 - jg1) <= CTX) ? fastexp(sacc[nt][3]) : 0.f;
                l0 += p00 + p01; l1 += p10 + p11;
                float h00 = f16_hi(p00), h01 = f16_hi(p01);
                float h10 = f16_hi(p10), h11 = f16_hi(p11);
                pah[nt >> 1][(nt & 1) * 2 + 0] = pack_f16(h00, h01);
                pah[nt >> 1][(nt & 1) * 2 + 1] = pack_f16(h10, h11);
                pal[nt >> 1][(nt & 1) * 2 + 0] = pack_f16(p00 - h00, p01 - h01);
                pal[nt >> 1][(nt & 1) * 2 + 1] = pack_f16(p10 - h10, p11 - h11);
            }

            // ---- GEMM2: O += P V (P split x2, V single fp16) ----
            #pragma unroll
            for (int ks = 0; ks < 2; ks++) {
                #pragma unroll
                for (int nt2 = 0; nt2 < 4; nt2++) {
                    uint32_t vh[4];
                    ldsm4t(vh, vtb + aoffV + ks * (16 * SP * 2) + nt2 * 32);
                    mma16816(oacc[2 * nt2],     pah[ks], vh);
                    mma16816(oacc[2 * nt2],     pal[ks], vh);
                    mma16816(oacc[2 * nt2 + 1], pah[ks], vh + 2);
                    mma16816(oacc[2 * nt2 + 1], pal[ks], vh + 2);
                }
            }
        }

        // ---- convert next chunk raw -> tiles(b^1) (own bytes; no barrier) ----
        if (ch < chhi) {
            CPA_WAIT0();
            const uint32_t kt = KT0 + (uint32_t)(b ^ 1) * TILE;
            const uint32_t vt = VT0 + (uint32_t)(b ^ 1) * TILE;
            #pragma unroll
            for (int it = 0; it < 4; it++) {
                int r = pr + it * 16;
                uint32_t roff = (uint32_t)(r * 64 + pc4) * 4;
                uint32_t boff = (uint32_t)(r * SP + pc4) * 2;
                float4 k4 = *(const float4*)(smem + RAWK + roff);
                *(uint2*)(smem + kt + boff) = make_uint2(pack_f16(k4.x, k4.y),
                                                         pack_f16(k4.z, k4.w));
                float4 v4 = *(const float4*)(smem + RAWV + roff);
                *(uint2*)(smem + vt + boff) = make_uint2(pack_f16(v4.x, v4.y),
                                                         pack_f16(v4.z, v4.w));
            }
        }
    }

    // ---- epilogue: reduce row sums + cross-warp O reduction ----
    l0 += __shfl_xor_sync(0xffffffffu, l0, 1);
    l0 += __shfl_xor_sync(0xffffffffu, l0, 2);
    l1 += __shfl_xor_sync(0xffffffffu, l1, 1);
    l1 += __shfl_xor_sync(0xffffffffu, l1, 2);
    float* Ls = (float*)(smem + LSM);
    if (qa == 0) {
        Ls[wc * 64 + wr * 16 + g]     = l0;
        Ls[wc * 64 + wr * 16 + g + 8] = l1;
    }
    __syncthreads();   // all MMA/ldmatrix reads done; safe to reuse smem

    float* Op = (float*)(smem + OPART);
    const int r0 = wr * 16 + g, r1 = r0 + 8;
    if (wc == 1) {
        #pragma unroll
        for (int nt = 0; nt < 8; nt++) {
            int c = nt * 8 + 2 * qa;
            *(float2*)&Op[r0 * 64 + c] = make_float2(oacc[nt][0], oacc[nt][1]);
            *(float2*)&Op[r1 * 64 + c] = make_float2(oacc[nt][2], oacc[nt][3]);
        }
    }
    __syncthreads();

    float* Ob = (float*)(smem + OBUF);
    if (wc == 0) {
        float inv0 = 1.0f / (Ls[r0] + Ls[64 + r0]);
        float inv1 = 1.0f / (Ls[r1] + Ls[64 + r1]);
        #pragma unroll
        for (int nt = 0; nt < 8; nt++) {
            int c = nt * 8 + 2 * qa;
            float2 q0 = *(float2*)&Op[r0 * 64 + c];
            float2 q1 = *(float2*)&Op[r1 * 64 + c];
            *(float2*)&Ob[r0 * 68 + c] = make_float2((oacc[nt][0] + q0.x) * inv0,
                                                     (oacc[nt][1] + q0.y) * inv0);
            *(float2*)&Ob[r1 * 68 + c] = make_float2((oacc[nt][2] + q1.x) * inv1,
                                                     (oacc[nt][3] + q1.y) * inv1);
        }
    }
    __syncthreads();

    for (int idx = t; idx < 64 * 16; idx += 256) {
        int r = idx >> 4, c4 = (idx & 15) * 4;
        float4 o4 = *(const float4*)&Ob[r * 68 + c4];
        *(float4*)&og[(size_t)(i0 + r) * DMODEL + hoff + c4] = o4;
    }
}

extern "C" void kernel_launch(void* const* d_in, const int* in_sizes, int n_in,
                              void* d_out, int out_size) {
    (void)in_sizes; (void)n_in; (void)out_size;
    const float* q = (const float*)d_in[0];
    const float* k = (const float*)d_in[1];
    const float* v = (const float*)d_in[2];
    float* o = (float*)d_out;

    cudaFuncSetAttribute(sparse_attn_mma,
                         cudaFuncAttributeMaxDynamicSharedMemorySize, SMEM_BYTES);
    dim3 grid(NSEQ / QT, HEADS);
    sparse_attn_mma<<<grid, 256, SMEM_BYTES>>>(q, k, v, o);
}

// round 8
// speedup vs baseline: 5.5574x; 1.2174x over previous
#include <cuda_runtime.h>
#include <cuda_fp16.h>
#include <cstdint>

#define NSEQ   2048
#define DMODEL 1024
#define HEADS  16
#define DH     64
#define CTX    128
#define QT     64
#define NCHUNK 5
#define SP     72            // padded smem row stride (fp16 elems) -> 144B
#define QSCALE 0.18033688011112042f   // 0.125 * log2(e): softmax = 2^s
#define TILE   (64*SP*2)     // 9216 B per 64x64 fp16 tile

// ---- smem byte offsets ----
#define QHI  0
#define QLO  (QHI + TILE)
#define KT0  (QLO + TILE)
#define KT1  (KT0 + TILE)
#define VT0  (KT1 + TILE)
#define VT1  (VT0 + TILE)
#define LSM  (VT0 + 2*TILE)          // 128 floats
#define RAWK (LSM + 512)             // fp32 staging 64x64
#define RAWV (RAWK + 16384)
#define SMEM_BYTES (RAWV + 16384)
#define OPART 0                      // epilogue reuse: 64x64 f32 partials
#define OBUF  KT0                    // epilogue reuse: 64x68 f32 staging

__device__ __forceinline__ uint32_t smem_u32(const void* p) {
    uint32_t a;
    asm("{ .reg .u64 t; cvta.to.shared.u64 t, %1; cvt.u32.u64 %0, t; }" : "=r"(a) : "l"(p));
    return a;
}
__device__ __forceinline__ void cpa16(uint32_t dst, const void* src) {
    asm volatile("cp.async.cg.shared.global [%0], [%1], 16;" :: "r"(dst), "l"(src));
}
#define CPA_COMMIT() asm volatile("cp.async.commit_group;" ::: "memory")
#define CPA_WAIT0()  asm volatile("cp.async.wait_group 0;" ::: "memory")

__device__ __forceinline__ void ldsm4(uint32_t* r, uint32_t a) {
    asm volatile("ldmatrix.sync.aligned.m8n8.x4.shared.b16 {%0,%1,%2,%3}, [%4];"
                 : "=r"(r[0]), "=r"(r[1]), "=r"(r[2]), "=r"(r[3]) : "r"(a));
}
__device__ __forceinline__ void ldsm4t(uint32_t* r, uint32_t a) {
    asm volatile("ldmatrix.sync.aligned.m8n8.x4.trans.shared.b16 {%0,%1,%2,%3}, [%4];"
                 : "=r"(r[0]), "=r"(r[1]), "=r"(r[2]), "=r"(r[3]) : "r"(a));
}
__device__ __forceinline__ void mma16816(float* c, const uint32_t* a, const uint32_t* b) {
    asm volatile("mma.sync.aligned.m16n8k16.row.col.f32.f16.f16.f32 "
                 "{%0,%1,%2,%3}, {%4,%5,%6,%7}, {%8,%9}, {%0,%1,%2,%3};"
                 : "+f"(c[0]), "+f"(c[1]), "+f"(c[2]), "+f"(c[3])
                 : "r"(a[0]), "r"(a[1]), "r"(a[2]), "r"(a[3]), "r"(b[0]), "r"(b[1]));
}
// pack two fp32 -> fp16x2 (first arg lands in low half)
__device__ __forceinline__ uint32_t pack_f16(float lo, float hi) {
    uint32_t r;
    asm("cvt.rn.f16x2.f32 %0, %1, %2;" : "=r"(r) : "f"(hi), "f"(lo));
    return r;
}
__device__ __forceinline__ float f16_hi(float x) {
    return __half2float(__float2half_rn(x));
}
// 2^x on the MUFU pipe (inputs bounded ~[-200, 12] here)
__device__ __forceinline__ float ex2a(float x) {
    float r; asm("ex2.approx.f32 %0, %1;" : "=f"(r) : "f"(x));
    return r;
}

__global__ void __launch_bounds__(256, 2)
sparse_attn_mma(const float* __restrict__ qg, const float* __restrict__ kg,
                const float* __restrict__ vg, float* __restrict__ og)
{
    extern __shared__ char smem[];
    const uint32_t sb = smem_u32(smem);
    const int t    = threadIdx.x;
    const int lane = t & 31, wid = t >> 5;
    const int wr   = wid & 3;          // row group: 16 rows
    const int wc   = wid >> 2;         // col group: 32 keys
    const int g    = lane >> 2;        // row-in-group (and +8)
    const int qa   = lane & 3;         // col pair selector
    const int h    = blockIdx.y;
    const int i0   = blockIdx.x * QT;
    const size_t hoff = (size_t)h * DH;

    // per-thread staging coords: each thread converts EXACTLY the bytes it
    // cp.async'd itself -> convert needs only wait_group 0, no barrier.
    const int pr = t >> 4, pc4 = (t & 15) * 4;

    // contiguous valid chunk range: jc in [0, NSEQ-64]
    const int chlo = (i0 >= CTX) ? 0 : (CTX - i0 + 63) / 64;
    const int chhi = min(NCHUNK - 1, (NSEQ - 64 - i0 + CTX) / 64);

    // ---- prologue: prefetch first chunk ----
    {
        const int jc = i0 - CTX + chlo * 64;
        #pragma unroll
        for (int it = 0; it < 4; it++) {
            int r = pr + it * 16;
            cpa16(sb + RAWK + (uint32_t)(r * 64 + pc4) * 4,
                  &kg[(size_t)(jc + r) * DMODEL + hoff + pc4]);
            cpa16(sb + RAWV + (uint32_t)(r * 64 + pc4) * 4,
                  &vg[(size_t)(jc + r) * DMODEL + hoff + pc4]);
        }
        CPA_COMMIT();
    }

    // ---- load Q once: scale (incl. log2e), split hi/lo fp16 ----
    for (int idx = t; idx < 64 * 16; idx += 256) {
        int r = idx >> 4, c4 = (idx & 15) * 4;
        float4 q4 = *(const float4*)&qg[(size_t)(i0 + r) * DMODEL + hoff + c4];
        q4.x *= QSCALE; q4.y *= QSCALE; q4.z *= QSCALE; q4.w *= QSCALE;
        float hx = f16_hi(q4.x), hy = f16_hi(q4.y), hz = f16_hi(q4.z), hw = f16_hi(q4.w);
        uint32_t boff = (uint32_t)(r * SP + c4) * 2;
        *(uint2*)(smem + QHI + boff) = make_uint2(pack_f16(hx, hy), pack_f16(hz, hw));
        *(uint2*)(smem + QLO + boff) = make_uint2(pack_f16(q4.x - hx, q4.y - hy),
                                                  pack_f16(q4.z - hz, q4.w - hw));
    }

    // ---- prologue convert: raw -> fp16 tiles (own bytes only) ----
    {
        CPA_WAIT0();
        const uint32_t kt = KT0 + (uint32_t)(chlo & 1) * TILE;
        const uint32_t vt = VT0 + (uint32_t)(chlo & 1) * TILE;
        #pragma unroll
        for (int it = 0; it < 4; it++) {
            int r = pr + it * 16;
            uint32_t roff = (uint32_t)(r * 64 + pc4) * 4;
            uint32_t boff = (uint32_t)(r * SP + pc4) * 2;
            float4 k4 = *(const float4*)(smem + RAWK + roff);
            *(uint2*)(smem + kt + boff) = make_uint2(pack_f16(k4.x, k4.y), pack_f16(k4.z, k4.w));
            float4 v4 = *(const float4*)(smem + RAWV + roff);
            *(uint2*)(smem + vt + boff) = make_uint2(pack_f16(v4.x, v4.y), pack_f16(v4.z, v4.w));
        }
    }

    // ldmatrix per-lane byte offsets
    const int l = lane;
    const uint32_t aoffA = (uint32_t)(((wr * 16 + (l & 15)) * SP + (l >> 4) * 8) * 2);
    const uint32_t aoffB = (uint32_t)(((wc * 32 + (l & 7) + ((l >> 4) & 1) * 8) * SP
                                      + ((l >> 3) & 1) * 8) * 2);
    const uint32_t aoffV = (uint32_t)(((wc * 32 + (l & 7) + ((l >> 3) & 1) * 8) * SP
                                      + ((l >> 4) & 1) * 8) * 2);

    float oacc[8][4];
    #pragma unroll
    for (int i = 0; i < 8; i++)
        #pragma unroll
        for (int j = 0; j < 4; j++) oacc[i][j] = 0.f;
    float l0 = 0.f, l1 = 0.f;

    const int ig0 = i0 + wr * 16 + g, ig1 = ig0 + 8;

    for (int ch = chlo; ch <= chhi; ch++) {
        const int b  = ch & 1;
        const int jc = i0 - CTX + ch * 64;

        __syncthreads();   // converts(ch) visible; all reads of tiles(b) from ch-2 done

        // ---- prefetch chunk ch+1 into raw staging (overlaps compute) ----
        if (ch < chhi) {
            const int jn = jc + 64;
            #pragma unroll
            for (int it = 0; it < 4; it++) {
                int r = pr + it * 16;
                cpa16(sb + RAWK + (uint32_t)(r * 64 + pc4) * 4,
                      &kg[(size_t)(jn + r) * DMODEL + hoff + pc4]);
                cpa16(sb + RAWV + (uint32_t)(r * 64 + pc4) * 4,
                      &vg[(size_t)(jn + r) * DMODEL + hoff + pc4]);
            }
            CPA_COMMIT();
        }

        // ---- skip warp tiles entirely outside the band (boundary chunks) ----
        const int doff = jc - i0;
        const bool active = !((doff + wc * 32 + 31 < wr * 16 - CTX) ||
                              (doff + wc * 32 > wr * 16 + 15 + CTX));
        if (active) {
            const uint32_t ktb = sb + KT0 + (uint32_t)b * TILE;
            const uint32_t vtb = sb + VT0 + (uint32_t)b * TILE;

            // ---- GEMM1: S = Q K^T (Q split x2, K single fp16) ----
            float sacc[4][4];
            #pragma unroll
            for (int i = 0; i < 4; i++)
                #pragma unroll
                for (int j = 0; j < 4; j++) sacc[i][j] = 0.f;

            #pragma unroll
            for (int k = 0; k < 4; k++) {
                uint32_t ah[4], al[4];
                ldsm4(ah, sb + QHI + aoffA + k * 32);
                ldsm4(al, sb + QLO + aoffA + k * 32);
                #pragma unroll
                for (int nt2 = 0; nt2 < 2; nt2++) {
                    uint32_t bh[4];
                    ldsm4(bh, ktb + aoffB + nt2 * (16 * SP * 2) + k * 32);
                    mma16816(sacc[2 * nt2],     ah, bh);
                    mma16816(sacc[2 * nt2],     al, bh);
                    mma16816(sacc[2 * nt2 + 1], ah, bh + 2);
                    mma16816(sacc[2 * nt2 + 1], al, bh + 2);
                }
            }

            // ---- softmax: p = 2^s (log2e folded into Q); mask only boundary chunks ----
            uint32_t pah[2][4];
            const bool needmask = (doff == -CTX) || (doff == CTX);
            if (needmask) {
                #pragma unroll
                for (int nt = 0; nt < 4; nt++) {
                    int jg0 = jc + wc * 32 + nt * 8 + 2 * qa, jg1 = jg0 + 1;
                    float p00 = ((unsigned)(jg0 - (ig0 - CTX)) <= 2u * CTX) ? ex2a(sacc[nt][0]) : 0.f;
                    float p01 = ((unsigned)(jg1 - (ig0 - CTX)) <= 2u * CTX) ? ex2a(sacc[nt][1]) : 0.f;
                    float p10 = ((unsigned)(jg0 - (ig1 - CTX)) <= 2u * CTX) ? ex2a(sacc[nt][2]) : 0.f;
                    float p11 = ((unsigned)(jg1 - (ig1 - CTX)) <= 2u * CTX) ? ex2a(sacc[nt][3]) : 0.f;
                    l0 += p00 + p01; l1 += p10 + p11;
                    pah[nt >> 1][(nt & 1) * 2 + 0] = pack_f16(p00, p01);
                    pah[nt >> 1][(nt & 1) * 2 + 1] = pack_f16(p10, p11);
                }
            } else {
                #pragma unroll
                for (int nt = 0; nt < 4; nt++) {
                    float p00 = ex2a(sacc[nt][0]);
                    float p01 = ex2a(sacc[nt][1]);
                    float p10 = ex2a(sacc[nt][2]);
                    float p11 = ex2a(sacc[nt][3]);
                    l0 += p00 + p01; l1 += p10 + p11;
                    pah[nt >> 1][(nt & 1) * 2 + 0] = pack_f16(p00, p01);
                    pah[nt >> 1][(nt & 1) * 2 + 1] = pack_f16(p10, p11);
                }
            }

            // ---- GEMM2: O += P V (single-rounded P, single V) ----
            #pragma unroll
            for (int ks = 0; ks < 2; ks++) {
                #pragma unroll
                for (int nt2 = 0; nt2 < 4; nt2++) {
                    uint32_t vh[4];
                    ldsm4t(vh, vtb + aoffV + ks * (16 * SP * 2) + nt2 * 32);
                    mma16816(oacc[2 * nt2],     pah[ks], vh);
                    mma16816(oacc[2 * nt2 + 1], pah[ks], vh + 2);
                }
            }
        }

        // ---- convert next chunk raw -> tiles(b^1) (own bytes; no barrier) ----
        if (ch < chhi) {
            CPA_WAIT0();
            const uint32_t kt = KT0 + (uint32_t)(b ^ 1) * TILE;
            const uint32_t vt = VT0 + (uint32_t)(b ^ 1) * TILE;
            #pragma unroll
            for (int it = 0; it < 4; it++) {
                int r = pr + it * 16;
                uint32_t roff = (uint32_t)(r * 64 + pc4) * 4;
                uint32_t boff = (uint32_t)(r * SP + pc4) * 2;
                float4 k4 = *(const float4*)(smem + RAWK + roff);
                *(uint2*)(smem + kt + boff) = make_uint2(pack_f16(k4.x, k4.y),
                                                         pack_f16(k4.z, k4.w));
                float4 v4 = *(const float4*)(smem + RAWV + roff);
                *(uint2*)(smem + vt + boff) = make_uint2(pack_f16(v4.x, v4.y),
                                                         pack_f16(v4.z, v4.w));
            }
        }
    }

    // ---- epilogue: reduce row sums + cross-warp O reduction ----
    l0 += __shfl_xor_sync(0xffffffffu, l0, 1);
    l0 += __shfl_xor_sync(0xffffffffu, l0, 2);
    l1 += __shfl_xor_sync(0xffffffffu, l1, 1);
    l1 += __shfl_xor_sync(0xffffffffu, l1, 2);
    float* Ls = (float*)(smem + LSM);
    if (qa == 0) {
        Ls[wc * 64 + wr * 16 + g]     = l0;
        Ls[wc * 64 + wr * 16 + g + 8] = l1;
    }
    __syncthreads();   // all MMA/ldmatrix reads done; safe to reuse smem

    float* Op = (float*)(smem + OPART);
    const int r0 = wr * 16 + g, r1 = r0 + 8;
    if (wc == 1) {
        #pragma unroll
        for (int nt = 0; nt < 8; nt++) {
            int c = nt * 8 + 2 * qa;
            *(float2*)&Op[r0 * 64 + c] = make_float2(oacc[nt][0], oacc[nt][1]);
            *(float2*)&Op[r1 * 64 + c] = make_float2(oacc[nt][2], oacc[nt][3]);
        }
    }
    __syncthreads();

    float* Ob = (float*)(smem + OBUF);
    if (wc == 0) {
        float inv0 = 1.0f / (Ls[r0] + Ls[64 + r0]);
        float inv1 = 1.0f / (Ls[r1] + Ls[64 + r1]);
        #pragma unroll
        for (int nt = 0; nt < 8; nt++) {
            int c = nt * 8 + 2 * qa;
            float2 q0 = *(float2*)&Op[r0 * 64 + c];
            float2 q1 = *(float2*)&Op[r1 * 64 + c];
            *(float2*)&Ob[r0 * 68 + c] = make_float2((oacc[nt][0] + q0.x) * inv0,
                                                     (oacc[nt][1] + q0.y) * inv0);
            *(float2*)&Ob[r1 * 68 + c] = make_float2((oacc[nt][2] + q1.x) * inv1,
                                                     (oacc[nt][3] + q1.y) * inv1);
        }
    }
    __syncthreads();

    for (int idx = t; idx < 64 * 16; idx += 256) {
        int r = idx >> 4, c4 = (idx & 15) * 4;
        float4 o4 = *(const float4*)&Ob[r * 68 + c4];
        *(float4*)&og[(size_t)(i0 + r) * DMODEL + hoff + c4] = o4;
    }
}

extern "C" void kernel_launch(void* const* d_in, const int* in_sizes, int n_in,
                              void* d_out, int out_size) {
    (void)in_sizes; (void)n_in; (void)out_size;
    const float* q = (const float*)d_in[0];
    const float* k = (const float*)d_in[1];
    const float* v = (const float*)d_in[2];
    float* o = (float*)d_out;

    cudaFuncSetAttribute(sparse_attn_mma,
                         cudaFuncAttributeMaxDynamicSharedMemorySize, SMEM_BYTES);
    dim3 grid(NSEQ / QT, HEADS);
    sparse_attn_mma<<<grid, 256, SMEM_BYTES>>>(q, k, v, o);
}

// round 9
// speedup vs baseline: 6.4824x; 1.1664x over previous
#include <cuda_runtime.h>
#include <cuda_fp16.h>
#include <cstdint>

#define NSEQ   2048
#define DMODEL 1024
#define HEADS  16
#define DH     64
#define CTX    128
#define QT     64
#define NCHUNK 5
#define SP     72            // padded smem row stride (fp16 elems) -> 144B
#define QSCALE 0.18033688011112042f   // 0.125 * log2(e): softmax = 2^s
#define TILE   (64*SP*2)     // 9216 B per 64x64 fp16 tile

// ---- smem byte offsets ----
#define QTI  0
#define KT0  (QTI + TILE)
#define KT1  (KT0 + TILE)
#define VT0  (KT1 + TILE)
#define VT1  (VT0 + TILE)
#define LSM  (VT0 + 2*TILE)          // 128 floats
#define RAWK (LSM + 512)             // fp32 staging 64x64
#define RAWV (RAWK + 16384)
#define SMEM_BYTES (RAWV + 16384)
// epilogue aliases (over K/V tiles, after final mainloop sync): 64x68 f32 each
#define OP0  KT0
#define OP1  (KT0 + 64*68*4)
#define OPS  68                      // f32 stride

__device__ __forceinline__ uint32_t smem_u32(const void* p) {
    uint32_t a;
    asm("{ .reg .u64 t; cvta.to.shared.u64 t, %1; cvt.u32.u64 %0, t; }" : "=r"(a) : "l"(p));
    return a;
}
__device__ __forceinline__ void cpa16(uint32_t dst, const void* src) {
    asm volatile("cp.async.cg.shared.global [%0], [%1], 16;" :: "r"(dst), "l"(src));
}
#define CPA_COMMIT() asm volatile("cp.async.commit_group;" ::: "memory")
#define CPA_WAIT0()  asm volatile("cp.async.wait_group 0;" ::: "memory")

__device__ __forceinline__ void ldsm4(uint32_t* r, uint32_t a) {
    asm volatile("ldmatrix.sync.aligned.m8n8.x4.shared.b16 {%0,%1,%2,%3}, [%4];"
                 : "=r"(r[0]), "=r"(r[1]), "=r"(r[2]), "=r"(r[3]) : "r"(a));
}
__device__ __forceinline__ void ldsm4t(uint32_t* r, uint32_t a) {
    asm volatile("ldmatrix.sync.aligned.m8n8.x4.trans.shared.b16 {%0,%1,%2,%3}, [%4];"
                 : "=r"(r[0]), "=r"(r[1]), "=r"(r[2]), "=r"(r[3]) : "r"(a));
}
__device__ __forceinline__ void mma16816(float* c, const uint32_t* a, const uint32_t* b) {
    asm volatile("mma.sync.aligned.m16n8k16.row.col.f32.f16.f16.f32 "
                 "{%0,%1,%2,%3}, {%4,%5,%6,%7}, {%8,%9}, {%0,%1,%2,%3};"
                 : "+f"(c[0]), "+f"(c[1]), "+f"(c[2]), "+f"(c[3])
                 : "r"(a[0]), "r"(a[1]), "r"(a[2]), "r"(a[3]), "r"(b[0]), "r"(b[1]));
}
// pack two fp32 -> fp16x2 (first arg lands in low half)
__device__ __forceinline__ uint32_t pack_f16(float lo, float hi) {
    uint32_t r;
    asm("cvt.rn.f16x2.f32 %0, %1, %2;" : "=r"(r) : "f"(hi), "f"(lo));
    return r;
}
// 2^x on the MUFU pipe
__device__ __forceinline__ float ex2a(float x) {
    float r; asm("ex2.approx.f32 %0, %1;" : "=f"(r) : "f"(x));
    return r;
}

__global__ void __launch_bounds__(256, 2)
sparse_attn_mma(const float* __restrict__ qg, const float* __restrict__ kg,
                const float* __restrict__ vg, float* __restrict__ og)
{
    extern __shared__ char smem[];
    const uint32_t sb = smem_u32(smem);
    const int t    = threadIdx.x;
    const int lane = t & 31, wid = t >> 5;
    const int wr   = wid & 3;          // row group: 16 rows
    const int wc   = wid >> 2;         // col group: 32 keys
    const int g    = lane >> 2;        // row-in-group (and +8)
    const int qa   = lane & 3;         // col pair selector
    const int h    = blockIdx.y;
    const int i0   = blockIdx.x * QT;
    const size_t hoff = (size_t)h * DH;

    // per-thread staging coords: each thread converts EXACTLY the bytes it
    // cp.async'd itself -> convert needs only wait_group 0, no barrier.
    const int pr = t >> 4, pc4 = (t & 15) * 4;

    // contiguous valid chunk range: jc in [0, NSEQ-64]
    const int chlo = (i0 >= CTX) ? 0 : (CTX - i0 + 63) / 64;
    const int chhi = min(NCHUNK - 1, (NSEQ - 64 - i0 + CTX) / 64);

    // ---- prologue: prefetch first chunk ----
    {
        const int jc = i0 - CTX + chlo * 64;
        #pragma unroll
        for (int it = 0; it < 4; it++) {
            int r = pr + it * 16;
            cpa16(sb + RAWK + (uint32_t)(r * 64 + pc4) * 4,
                  &kg[(size_t)(jc + r) * DMODEL + hoff + pc4]);
            cpa16(sb + RAWV + (uint32_t)(r * 64 + pc4) * 4,
                  &vg[(size_t)(jc + r) * DMODEL + hoff + pc4]);
        }
        CPA_COMMIT();
    }

    // ---- load Q once: scale (incl. log2e), single fp16 ----
    for (int idx = t; idx < 64 * 16; idx += 256) {
        int r = idx >> 4, c4 = (idx & 15) * 4;
        float4 q4 = *(const float4*)&qg[(size_t)(i0 + r) * DMODEL + hoff + c4];
        q4.x *= QSCALE; q4.y *= QSCALE; q4.z *= QSCALE; q4.w *= QSCALE;
        uint32_t boff = (uint32_t)(r * SP + c4) * 2;
        *(uint2*)(smem + QTI + boff) = make_uint2(pack_f16(q4.x, q4.y), pack_f16(q4.z, q4.w));
    }

    // ---- prologue convert: raw -> fp16 tiles (own bytes only) ----
    {
        CPA_WAIT0();
        const uint32_t kt = KT0 + (uint32_t)(chlo & 1) * TILE;
        const uint32_t vt = VT0 + (uint32_t)(chlo & 1) * TILE;
        #pragma unroll
        for (int it = 0; it < 4; it++) {
            int r = pr + it * 16;
            uint32_t roff = (uint32_t)(r * 64 + pc4) * 4;
            uint32_t boff = (uint32_t)(r * SP + pc4) * 2;
            float4 k4 = *(const float4*)(smem + RAWK + roff);
            *(uint2*)(smem + kt + boff) = make_uint2(pack_f16(k4.x, k4.y), pack_f16(k4.z, k4.w));
            float4 v4 = *(const float4*)(smem + RAWV + roff);
            *(uint2*)(smem + vt + boff) = make_uint2(pack_f16(v4.x, v4.y), pack_f16(v4.z, v4.w));
        }
    }
    __syncthreads();   // Q tile + first converts visible to all warps

    // ldmatrix per-lane byte offsets
    const int l = lane;
    const uint32_t aoffA = (uint32_t)(((wr * 16 + (l & 15)) * SP + (l >> 4) * 8) * 2);
    const uint32_t aoffB = (uint32_t)(((wc * 32 + (l & 7) + ((l >> 4) & 1) * 8) * SP
                                      + ((l >> 3) & 1) * 8) * 2);
    const uint32_t aoffV = (uint32_t)(((wc * 32 + (l & 7) + ((l >> 3) & 1) * 8) * SP
                                      + ((l >> 4) & 1) * 8) * 2);

    // ---- hoist Q fragments into registers (chunk-invariant) ----
    uint32_t aq[4][4];
    #pragma unroll
    for (int k = 0; k < 4; k++)
        ldsm4(aq[k], sb + QTI + aoffA + k * 32);

    float oacc[8][4];
    #pragma unroll
    for (int i = 0; i < 8; i++)
        #pragma unroll
        for (int j = 0; j < 4; j++) oacc[i][j] = 0.f;
    float l0 = 0.f, l1 = 0.f;

    const int ig0 = i0 + wr * 16 + g, ig1 = ig0 + 8;

    for (int ch = chlo; ch <= chhi; ch++) {
        const int b  = ch & 1;
        const int jc = i0 - CTX + ch * 64;

        // ---- prefetch chunk ch+1 into raw staging (overlaps compute) ----
        if (ch < chhi) {
            const int jn = jc + 64;
            #pragma unroll
            for (int it = 0; it < 4; it++) {
                int r = pr + it * 16;
                cpa16(sb + RAWK + (uint32_t)(r * 64 + pc4) * 4,
                      &kg[(size_t)(jn + r) * DMODEL + hoff + pc4]);
                cpa16(sb + RAWV + (uint32_t)(r * 64 + pc4) * 4,
                      &vg[(size_t)(jn + r) * DMODEL + hoff + pc4]);
            }
            CPA_COMMIT();
        }

        // ---- skip warp tiles entirely outside the band (boundary chunks) ----
        const int doff = jc - i0;
        const bool active = !((doff + wc * 32 + 31 < wr * 16 - CTX) ||
                              (doff + wc * 32 > wr * 16 + 15 + CTX));
        if (active) {
            const uint32_t ktb = sb + KT0 + (uint32_t)b * TILE;
            const uint32_t vtb = sb + VT0 + (uint32_t)b * TILE;

            // ---- GEMM1: S = Q K^T (single fp16, Q frags hoisted) ----
            float sacc[4][4];
            #pragma unroll
            for (int i = 0; i < 4; i++)
                #pragma unroll
                for (int j = 0; j < 4; j++) sacc[i][j] = 0.f;

            #pragma unroll
            for (int k = 0; k < 4; k++) {
                #pragma unroll
                for (int nt2 = 0; nt2 < 2; nt2++) {
                    uint32_t bh[4];
                    ldsm4(bh, ktb + aoffB + nt2 * (16 * SP * 2) + k * 32);
                    mma16816(sacc[2 * nt2],     aq[k], bh);
                    mma16816(sacc[2 * nt2 + 1], aq[k], bh + 2);
                }
            }

            // ---- softmax: p = 2^s (log2e folded into Q); mask only boundary chunks ----
            uint32_t pah[2][4];
            const bool needmask = (doff == -CTX) || (doff == CTX);
            if (needmask) {
                #pragma unroll
                for (int nt = 0; nt < 4; nt++) {
                    int jg0 = jc + wc * 32 + nt * 8 + 2 * qa, jg1 = jg0 + 1;
                    float p00 = ((unsigned)(jg0 - (ig0 - CTX)) <= 2u * CTX) ? ex2a(sacc[nt][0]) : 0.f;
                    float p01 = ((unsigned)(jg1 - (ig0 - CTX)) <= 2u * CTX) ? ex2a(sacc[nt][1]) : 0.f;
                    float p10 = ((unsigned)(jg0 - (ig1 - CTX)) <= 2u * CTX) ? ex2a(sacc[nt][2]) : 0.f;
                    float p11 = ((unsigned)(jg1 - (ig1 - CTX)) <= 2u * CTX) ? ex2a(sacc[nt][3]) : 0.f;
                    l0 += p00 + p01; l1 += p10 + p11;
                    pah[nt >> 1][(nt & 1) * 2 + 0] = pack_f16(p00, p01);
                    pah[nt >> 1][(nt & 1) * 2 + 1] = pack_f16(p10, p11);
                }
            } else {
                #pragma unroll
                for (int nt = 0; nt < 4; nt++) {
                    float p00 = ex2a(sacc[nt][0]);
                    float p01 = ex2a(sacc[nt][1]);
                    float p10 = ex2a(sacc[nt][2]);
                    float p11 = ex2a(sacc[nt][3]);
                    l0 += p00 + p01; l1 += p10 + p11;
                    pah[nt >> 1][(nt & 1) * 2 + 0] = pack_f16(p00, p01);
                    pah[nt >> 1][(nt & 1) * 2 + 1] = pack_f16(p10, p11);
                }
            }

            // ---- GEMM2: O += P V (single-rounded P, single V) ----
            #pragma unroll
            for (int ks = 0; ks < 2; ks++) {
                #pragma unroll
                for (int nt2 = 0; nt2 < 4; nt2++) {
                    uint32_t vh[4];
                    ldsm4t(vh, vtb + aoffV + ks * (16 * SP * 2) + nt2 * 32);
                    mma16816(oacc[2 * nt2],     pah[ks], vh);
                    mma16816(oacc[2 * nt2 + 1], pah[ks], vh + 2);
                }
            }
        }

        // ---- convert next chunk raw -> tiles(b^1) (own bytes; no barrier) ----
        if (ch < chhi) {
            CPA_WAIT0();
            const uint32_t kt = KT0 + (uint32_t)(b ^ 1) * TILE;
            const uint32_t vt = VT0 + (uint32_t)(b ^ 1) * TILE;
            #pragma unroll
            for (int it = 0; it < 4; it++) {
                int r = pr + it * 16;
                uint32_t roff = (uint32_t)(r * 64 + pc4) * 4;
                uint32_t boff = (uint32_t)(r * SP + pc4) * 2;
                float4 k4 = *(const float4*)(smem + RAWK + roff);
                *(uint2*)(smem + kt + boff) = make_uint2(pack_f16(k4.x, k4.y),
                                                         pack_f16(k4.z, k4.w));
                float4 v4 = *(const float4*)(smem + RAWV + roff);
                *(uint2*)(smem + vt + boff) = make_uint2(pack_f16(v4.x, v4.y),
                                                         pack_f16(v4.z, v4.w));
            }
        }
        __syncthreads();   // converts visible; tile(b) reads complete before next overwrite
    }
    // (final loop sync also fences the epilogue's reuse of the tile region)

    // ---- epilogue: row sums + both warp-groups dump O partials ----
    l0 += __shfl_xor_sync(0xffffffffu, l0, 1);
    l0 += __shfl_xor_sync(0xffffffffu, l0, 2);
    l1 += __shfl_xor_sync(0xffffffffu, l1, 1);
    l1 += __shfl_xor_sync(0xffffffffu, l1, 2);
    float* Ls = (float*)(smem + LSM);
    const int r0 = wr * 16 + g, r1 = r0 + 8;
    if (qa == 0) {
        Ls[wc * 64 + r0] = l0;
        Ls[wc * 64 + r1] = l1;
    }
    {
        float* Op = (float*)(smem + (wc ? OP1 : OP0));
        #pragma unroll
        for (int nt = 0; nt < 8; nt++) {
            int c = nt * 8 + 2 * qa;
            *(float2*)&Op[r0 * OPS + c] = make_float2(oacc[nt][0], oacc[nt][1]);
            *(float2*)&Op[r1 * OPS + c] = make_float2(oacc[nt][2], oacc[nt][3]);
        }
    }
    __syncthreads();

    // ---- final: add partials, normalize, store coalesced ----
    const float* P0 = (const float*)(smem + OP0);
    const float* P1 = (const float*)(smem + OP1);
    for (int idx = t; idx < 64 * 16; idx += 256) {
        int r = idx >> 4, c4 = (idx & 15) * 4;
        float inv = 1.0f / (Ls[r] + Ls[64 + r]);
        float4 a = *(const float4*)&P0[r * OPS + c4];
        float4 b = *(const float4*)&P1[r * OPS + c4];
        float4 o4;
        o4.x = (a.x + b.x) * inv;
        o4.y = (a.y + b.y) * inv;
        o4.z = (a.z + b.z) * inv;
        o4.w = (a.w + b.w) * inv;
        *(float4*)&og[(size_t)(i0 + r) * DMODEL + hoff + c4] = o4;
    }
}

extern "C" void kernel_launch(void* const* d_in, const int* in_sizes, int n_in,
                              void* d_out, int out_size) {
    (void)in_sizes; (void)n_in; (void)out_size;
    const float* q = (const float*)d_in[0];
    const float* k = (const float*)d_in[1];
    const float* v = (const float*)d_in[2];
    float* o = (float*)d_out;

    cudaFuncSetAttribute(sparse_attn_mma,
                         cudaFuncAttributeMaxDynamicSharedMemorySize, SMEM_BYTES);
    dim3 grid(NSEQ / QT, HEADS);
    sparse_attn_mma<<<grid, 256, SMEM_BYTES>>>(q, k, v, o);
}

// round 11
// speedup vs baseline: 6.4909x; 1.0013x over previous
#include <cuda_runtime.h>
#include <cuda_fp16.h>
#include <cstdint>

#define NSEQ   2048
#define DMODEL 1024
#define HEADS  16
#define DH     64
#define CTX    128
#define QT     64
#define NCHUNK 5
#define SP     72            // padded smem row stride (fp16 elems) -> 144B
#define QSCALE 0.18033688011112042f   // 0.125 * log2(e): softmax = 2^s
#define TILE   (64*SP*2)     // 9216 B per 64x64 fp16 tile

// ---- smem byte offsets ----
#define QTI  0
#define KT0  (QTI + TILE)
#define KT1  (KT0 + TILE)
#define VT0  (KT1 + TILE)
#define VT1  (VT0 + TILE)
#define LSM  (VT0 + 2*TILE)          // 128 floats
#define RAWK (LSM + 512)             // fp32 staging 64x64
#define RAWV (RAWK + 16384)
#define SMEM_BYTES (RAWV + 16384)
// epilogue aliases (over K/V tiles, AFTER a full __syncthreads): 64x68 f32 each
#define OP0  KT0
#define OP1  (KT0 + 64*68*4)
#define OPS  68                      // f32 stride

__device__ __forceinline__ uint32_t smem_u32(const void* p) {
    uint32_t a;
    asm("{ .reg .u64 t; cvta.to.shared.u64 t, %1; cvt.u32.u64 %0, t; }" : "=r"(a) : "l"(p));
    return a;
}
__device__ __forceinline__ void cpa16(uint32_t dst, const void* src) {
    asm volatile("cp.async.cg.shared.global [%0], [%1], 16;" :: "r"(dst), "l"(src));
}
#define CPA_COMMIT() asm volatile("cp.async.commit_group;" ::: "memory")
#define CPA_WAIT0()  asm volatile("cp.async.wait_group 0;" ::: "memory")
// half-CTA barrier: group g (128 threads) syncs on named barrier 1+g
#define BAR_GRP(gid) asm volatile("bar.sync %0, 128;" :: "r"(1 + (gid)) : "memory")

__device__ __forceinline__ void ldsm4(uint32_t* r, uint32_t a) {
    asm volatile("ldmatrix.sync.aligned.m8n8.x4.shared.b16 {%0,%1,%2,%3}, [%4];"
                 : "=r"(r[0]), "=r"(r[1]), "=r"(r[2]), "=r"(r[3]) : "r"(a));
}
__device__ __forceinline__ void ldsm4t(uint32_t* r, uint32_t a) {
    asm volatile("ldmatrix.sync.aligned.m8n8.x4.trans.shared.b16 {%0,%1,%2,%3}, [%4];"
                 : "=r"(r[0]), "=r"(r[1]), "=r"(r[2]), "=r"(r[3]) : "r"(a));
}
__device__ __forceinline__ void mma16816(float* c, const uint32_t* a, const uint32_t* b) {
    asm volatile("mma.sync.aligned.m16n8k16.row.col.f32.f16.f16.f32 "
                 "{%0,%1,%2,%3}, {%4,%5,%6,%7}, {%8,%9}, {%0,%1,%2,%3};"
                 : "+f"(c[0]), "+f"(c[1]), "+f"(c[2]), "+f"(c[3])
                 : "r"(a[0]), "r"(a[1]), "r"(a[2]), "r"(a[3]), "r"(b[0]), "r"(b[1]));
}
// pack two fp32 -> fp16x2 (first arg lands in low half)
__device__ __forceinline__ uint32_t pack_f16(float lo, float hi) {
    uint32_t r;
    asm("cvt.rn.f16x2.f32 %0, %1, %2;" : "=r"(r) : "f"(hi), "f"(lo));
    return r;
}
// 2^x on the MUFU pipe
__device__ __forceinline__ float ex2a(float x) {
    float r; asm("ex2.approx.f32 %0, %1;" : "=f"(r) : "f"(x));
    return r;
}

__global__ void __launch_bounds__(256, 2)
sparse_attn_mma(const float* __restrict__ qg, const float* __restrict__ kg,
                const float* __restrict__ vg, float* __restrict__ og)
{
    extern __shared__ char smem[];
    const uint32_t sb = smem_u32(smem);
    const int t    = threadIdx.x;
    const int lane = t & 31, wid = t >> 5;
    const int wr   = wid & 3;          // row group: 16 rows
    const int wc   = wid >> 2;         // col group: 32 keys (== thread group id)
    const int grp  = t >> 7;           // 0/1 half-CTA (== wc for this thread's warp)
    const int g    = lane >> 2;        // row-in-group (and +8)
    const int qa   = lane & 3;         // col pair selector
    const int h    = blockIdx.y;
    const int i0   = blockIdx.x * QT;
    const size_t hoff = (size_t)h * DH;

    // group-local staging coords: group grp owns K/V rows [grp*32, grp*32+32).
    // Each thread cp.asyncs AND converts exactly its own bytes -> within-group
    // visibility needs only the group barrier; groups share nothing in the loop.
    const int tl  = t & 127;
    const int pr  = grp * 32 + (tl >> 4);    // +8 per pass, 4 passes -> 32 rows
    const int pc4 = (tl & 15) * 4;

    // contiguous valid chunk range: jc in [0, NSEQ-64]
    const int chlo = (i0 >= CTX) ? 0 : (CTX - i0 + 63) / 64;
    const int chhi = min(NCHUNK - 1, (NSEQ - 64 - i0 + CTX) / 64);

    // ---- prologue: prefetch first chunk (own rows) ----
    {
        const int jc = i0 - CTX + chlo * 64;
        #pragma unroll
        for (int it = 0; it < 4; it++) {
            int r = pr + it * 8;
            cpa16(sb + RAWK + (uint32_t)(r * 64 + pc4) * 4,
                  &kg[(size_t)(jc + r) * DMODEL + hoff + pc4]);
            cpa16(sb + RAWV + (uint32_t)(r * 64 + pc4) * 4,
                  &vg[(size_t)(jc + r) * DMODEL + hoff + pc4]);
        }
        CPA_COMMIT();
    }

    // ---- load Q once: scale (incl. log2e), single fp16 ----
    for (int idx = t; idx < 64 * 16; idx += 256) {
        int r = idx >> 4, c4 = (idx & 15) * 4;
        float4 q4 = *(const float4*)&qg[(size_t)(i0 + r) * DMODEL + hoff + c4];
        q4.x *= QSCALE; q4.y *= QSCALE; q4.z *= QSCALE; q4.w *= QSCALE;
        uint32_t boff = (uint32_t)(r * SP + c4) * 2;
        *(uint2*)(smem + QTI + boff) = make_uint2(pack_f16(q4.x, q4.y), pack_f16(q4.z, q4.w));
    }

    // ---- prologue convert: raw -> fp16 tiles (own bytes only) ----
    {
        CPA_WAIT0();
        const uint32_t kt = KT0 + (uint32_t)(chlo & 1) * TILE;
        const uint32_t vt = VT0 + (uint32_t)(chlo & 1) * TILE;
        #pragma unroll
        for (int it = 0; it < 4; it++) {
            int r = pr + it * 8;
            uint32_t roff = (uint32_t)(r * 64 + pc4) * 4;
            uint32_t boff = (uint32_t)(r * SP + pc4) * 2;
            float4 k4 = *(const float4*)(smem + RAWK + roff);
            *(uint2*)(smem + kt + boff) = make_uint2(pack_f16(k4.x, k4.y), pack_f16(k4.z, k4.w));
            float4 v4 = *(const float4*)(smem + RAWV + roff);
            *(uint2*)(smem + vt + boff) = make_uint2(pack_f16(v4.x, v4.y), pack_f16(v4.z, v4.w));
        }
    }
    __syncthreads();   // Q tile + both groups' first converts visible

    // ldmatrix per-lane byte offsets
    const int l = lane;
    const uint32_t aoffA = (uint32_t)(((wr * 16 + (l & 15)) * SP + (l >> 4) * 8) * 2);
    const uint32_t aoffB = (uint32_t)(((wc * 32 + (l & 7) + ((l >> 4) & 1) * 8) * SP
                                      + ((l >> 3) & 1) * 8) * 2);
    const uint32_t aoffV = (uint32_t)(((wc * 32 + (l & 7) + ((l >> 3) & 1) * 8) * SP
                                      + ((l >> 4) & 1) * 8) * 2);

    // ---- hoist Q fragments into registers (chunk-invariant) ----
    uint32_t aq[4][4];
    #pragma unroll
    for (int k = 0; k < 4; k++)
        ldsm4(aq[k], sb + QTI + aoffA + k * 32);

    float oacc[8][4];
    #pragma unroll
    for (int i = 0; i < 8; i++)
        #pragma unroll
        for (int j = 0; j < 4; j++) oacc[i][j] = 0.f;
    float l0 = 0.f, l1 = 0.f;

    const int ig0 = i0 + wr * 16 + g, ig1 = ig0 + 8;

    for (int ch = chlo; ch <= chhi; ch++) {
        const int b  = ch & 1;
        const int jc = i0 - CTX + ch * 64;

        // ---- prefetch chunk ch+1 (own rows; overlaps compute) ----
        if (ch < chhi) {
            const int jn = jc + 64;
            #pragma unroll
            for (int it = 0; it < 4; it++) {
                int r = pr + it * 8;
                cpa16(sb + RAWK + (uint32_t)(r * 64 + pc4) * 4,
                      &kg[(size_t)(jn + r) * DMODEL + hoff + pc4]);
                cpa16(sb + RAWV + (uint32_t)(r * 64 + pc4) * 4,
                      &vg[(size_t)(jn + r) * DMODEL + hoff + pc4]);
            }
            CPA_COMMIT();
        }

        // ---- skip warp tiles entirely outside the band (boundary chunks) ----
        const int doff = jc - i0;
        const bool active = !((doff + wc * 32 + 31 < wr * 16 - CTX) ||
                              (doff + wc * 32 > wr * 16 + 15 + CTX));
        if (active) {
            const uint32_t ktb = sb + KT0 + (uint32_t)b * TILE;
            const uint32_t vtb = sb + VT0 + (uint32_t)b * TILE;

            // ---- GEMM1: S = Q K^T (single fp16, Q frags hoisted) ----
            float sacc[4][4];
            #pragma unroll
            for (int i = 0; i < 4; i++)
                #pragma unroll
                for (int j = 0; j < 4; j++) sacc[i][j] = 0.f;

            #pragma unroll
            for (int k = 0; k < 4; k++) {
                #pragma unroll
                for (int nt2 = 0; nt2 < 2; nt2++) {
                    uint32_t bh[4];
                    ldsm4(bh, ktb + aoffB + nt2 * (16 * SP * 2) + k * 32);
                    mma16816(sacc[2 * nt2],     aq[k], bh);
                    mma16816(sacc[2 * nt2 + 1], aq[k], bh + 2);
                }
            }

            // ---- softmax: p = 2^s (log2e folded into Q); mask only boundary chunks ----
            uint32_t pah[2][4];
            const bool needmask = (doff == -CTX) || (doff == CTX);
            if (needmask) {
                #pragma unroll
                for (int nt = 0; nt < 4; nt++) {
                    int jg0 = jc + wc * 32 + nt * 8 + 2 * qa, jg1 = jg0 + 1;
                    float p00 = ((unsigned)(jg0 - (ig0 - CTX)) <= 2u * CTX) ? ex2a(sacc[nt][0]) : 0.f;
                    float p01 = ((unsigned)(jg1 - (ig0 - CTX)) <= 2u * CTX) ? ex2a(sacc[nt][1]) : 0.f;
                    float p10 = ((unsigned)(jg0 - (ig1 - CTX)) <= 2u * CTX) ? ex2a(sacc[nt][2]) : 0.f;
                    float p11 = ((unsigned)(jg1 - (ig1 - CTX)) <= 2u * CTX) ? ex2a(sacc[nt][3]) : 0.f;
                    l0 += p00 + p01; l1 += p10 + p11;
                    pah[nt >> 1][(nt & 1) * 2 + 0] = pack_f16(p00, p01);
                    pah[nt >> 1][(nt & 1) * 2 + 1] = pack_f16(p10, p11);
                }
            } else {
                #pragma unroll
                for (int nt = 0; nt < 4; nt++) {
                    float p00 = ex2a(sacc[nt][0]);
                    float p01 = ex2a(sacc[nt][1]);
                    float p10 = ex2a(sacc[nt][2]);
                    float p11 = ex2a(sacc[nt][3]);
                    l0 += p00 + p01; l1 += p10 + p11;
                    pah[nt >> 1][(nt & 1) * 2 + 0] = pack_f16(p00, p01);
                    pah[nt >> 1][(nt & 1) * 2 + 1] = pack_f16(p10, p11);
                }
            }

            // ---- GEMM2: O += P V (single-rounded P, single V) ----
            #pragma unroll
            for (int ks = 0; ks < 2; ks++) {
                #pragma unroll
                for (int nt2 = 0; nt2 < 4; nt2++) {
                    uint32_t vh[4];
                    ldsm4t(vh, vtb + aoffV + ks * (16 * SP * 2) + nt2 * 32);
                    mma16816(oacc[2 * nt2],     pah[ks], vh);
                    mma16816(oacc[2 * nt2 + 1], pah[ks], vh + 2);
                }
            }
        }

        // ---- convert next chunk raw -> tiles(b^1) (own bytes; self-visible) ----
        if (ch < chhi) {
            CPA_WAIT0();
            const uint32_t kt = KT0 + (uint32_t)(b ^ 1) * TILE;
            const uint32_t vt = VT0 + (uint32_t)(b ^ 1) * TILE;
            #pragma unroll
            for (int it = 0; it < 4; it++) {
                int r = pr + it * 8;
                uint32_t roff = (uint32_t)(r * 64 + pc4) * 4;
                uint32_t boff = (uint32_t)(r * SP + pc4) * 2;
                float4 k4 = *(const float4*)(smem + RAWK + roff);
                *(uint2*)(smem + kt + boff) = make_uint2(pack_f16(k4.x, k4.y),
                                                         pack_f16(k4.z, k4.w));
                float4 v4 = *(const float4*)(smem + RAWV + roff);
                *(uint2*)(smem + vt + boff) = make_uint2(pack_f16(v4.x, v4.y),
                                                         pack_f16(v4.z, v4.w));
            }
        }
        BAR_GRP(grp);   // half-CTA barrier: converts visible within group;
                        // group's tile(b) reads complete before its next overwrite
    }

    __syncthreads();   // both groups done with K/V tiles before epilogue aliases them

    // ---- epilogue: row sums + both groups dump O partials ----
    l0 += __shfl_xor_sync(0xffffffffu, l0, 1);
    l0 += __shfl_xor_sync(0xffffffffu, l0, 2);
    l1 += __shfl_xor_sync(0xffffffffu, l1, 1);
    l1 += __shfl_xor_sync(0xffffffffu, l1, 2);
    float* Ls = (float*)(smem + LSM);
    const int r0 = wr * 16 + g, r1 = r0 + 8;
    if (qa == 0) {
        Ls[wc * 64 + r0] = l0;
        Ls[wc * 64 + r1] = l1;
    }
    {
        float* Op = (float*)(smem + (wc ? OP1 : OP0));
        #pragma unroll
        for (int nt = 0; nt < 8; nt++) {
            int c = nt * 8 + 2 * qa;
            *(float2*)&Op[r0 * OPS + c] = make_float2(oacc[nt][0], oacc[nt][1]);
            *(float2*)&Op[r1 * OPS + c] = make_float2(oacc[nt][2], oacc[nt][3]);
        }
    }
    __syncthreads();

    // ---- final: add partials, normalize, store coalesced ----
    const float* P0 = (const float*)(smem + OP0);
    const float* P1 = (const float*)(smem + OP1);
    for (int idx = t; idx < 64 * 16; idx += 256) {
        int r = idx >> 4, c4 = (idx & 15) * 4;
        float inv = 1.0f / (Ls[r] + Ls[64 + r]);
        float4 a = *(const float4*)&P0[r * OPS + c4];
        float4 b = *(const float4*)&P1[r * OPS + c4];
        float4 o4;
        o4.x = (a.x + b.x) * inv;
        o4.y = (a.y + b.y) * inv;
        o4.z = (a.z + b.z) * inv;
        o4.w = (a.w + b.w) * inv;
        *(float4*)&og[(size_t)(i0 + r) * DMODEL + hoff + c4] = o4;
    }
}

extern "C" void kernel_launch(void* const* d_in, const int* in_sizes, int n_in,
                              void* d_out, int out_size) {
    (void)in_sizes; (void)n_in; (void)out_size;
    const float* q = (const float*)d_in[0];
    const float* k = (const float*)d_in[1];
    const float* v = (const float*)d_in[2];
    float* o = (float*)d_out;

    cudaFuncSetAttribute(sparse_attn_mma,
                         cudaFuncAttributeMaxDynamicSharedMemorySize, SMEM_BYTES);
    dim3 grid(NSEQ / QT, HEADS);
    sparse_attn_mma<<<grid, 256, SMEM_BYTES>>>(q, k, v, o);
}

// round 12
// speedup vs baseline: 7.5760x; 1.1672x over previous
#include <cuda_runtime.h>
#include <cuda_fp16.h>
#include <cstdint>

#define NSEQ   2048
#define DMODEL 1024
#define HEADS  16
#define DH     64
#define CTX    128
#define QT     128
#define NCHUNK 6
#define SP     72            // padded smem row stride (fp16 elems) -> 144B
#define QSCALE 0.18033688011112042f   // 0.125 * log2(e): softmax = 2^s
#define KVTILE (64*SP*2)     // 9216 B per 64x64 fp16 tile

// ---- smem byte offsets ----
#define QTI  0                        // 128xSP fp16 = 18432
#define KT0  18432
#define KT1  (KT0 + KVTILE)
#define VT0  (KT1 + KVTILE)
#define VT1  (VT0 + KVTILE)
#define RAWK (VT1 + KVTILE)          // fp32 staging 64x64
#define RAWV (RAWK + 16384)
#define SMEM_BYTES (RAWV + 16384)
// epilogue alias (over K/V tiles, AFTER a full __syncthreads): 128x68 f32
#define OB   KT0
#define OPS  68

__device__ __forceinline__ uint32_t smem_u32(const void* p) {
    uint32_t a;
    asm("{ .reg .u64 t; cvta.to.shared.u64 t, %1; cvt.u32.u64 %0, t; }" : "=r"(a) : "l"(p));
    return a;
}
__device__ __forceinline__ void cpa16(uint32_t dst, const void* src) {
    asm volatile("cp.async.cg.shared.global [%0], [%1], 16;" :: "r"(dst), "l"(src));
}
#define CPA_COMMIT() asm volatile("cp.async.commit_group;" ::: "memory")
#define CPA_WAIT0()  asm volatile("cp.async.wait_group 0;" ::: "memory")

__device__ __forceinline__ void ldsm4(uint32_t* r, uint32_t a) {
    asm volatile("ldmatrix.sync.aligned.m8n8.x4.shared.b16 {%0,%1,%2,%3}, [%4];"
                 : "=r"(r[0]), "=r"(r[1]), "=r"(r[2]), "=r"(r[3]) : "r"(a));
}
__device__ __forceinline__ void ldsm4t(uint32_t* r, uint32_t a) {
    asm volatile("ldmatrix.sync.aligned.m8n8.x4.trans.shared.b16 {%0,%1,%2,%3}, [%4];"
                 : "=r"(r[0]), "=r"(r[1]), "=r"(r[2]), "=r"(r[3]) : "r"(a));
}
__device__ __forceinline__ void mma16816(float* c, const uint32_t* a, const uint32_t* b) {
    asm volatile("mma.sync.aligned.m16n8k16.row.col.f32.f16.f16.f32 "
                 "{%0,%1,%2,%3}, {%4,%5,%6,%7}, {%8,%9}, {%0,%1,%2,%3};"
                 : "+f"(c[0]), "+f"(c[1]), "+f"(c[2]), "+f"(c[3])
                 : "r"(a[0]), "r"(a[1]), "r"(a[2]), "r"(a[3]), "r"(b[0]), "r"(b[1]));
}
// pack two fp32 -> fp16x2 (first arg lands in low half)
__device__ __forceinline__ uint32_t pack_f16(float lo, float hi) {
    uint32_t r;
    asm("cvt.rn.f16x2.f32 %0, %1, %2;" : "=r"(r) : "f"(hi), "f"(lo));
    return r;
}
// 2^x on the MUFU pipe
__device__ __forceinline__ float ex2a(float x) {
    float r; asm("ex2.approx.f32 %0, %1;" : "=f"(r) : "f"(x));
    return r;
}

__global__ void __launch_bounds__(256, 2)
sparse_attn_mma(const float* __restrict__ qg, const float* __restrict__ kg,
                const float* __restrict__ vg, float* __restrict__ og)
{
    extern __shared__ char smem[];
    const uint32_t sb = smem_u32(smem);
    const int t    = threadIdx.x;
    const int lane = t & 31, wid = t >> 5;
    const int wr   = wid;              // row group: 16 rows, warp owns all 64 chunk cols
    const int g    = lane >> 2;        // row-in-group (and +8)
    const int qa   = lane & 3;         // col pair selector
    const int h    = blockIdx.y;
    const int i0   = blockIdx.x * QT;
    const size_t hoff = (size_t)h * DH;

    // staging coords: each thread cp.asyncs AND converts exactly its own bytes
    // -> convert needs only wait_group 0 + the per-chunk barrier.
    const int pr  = t >> 4;            // +16 per pass, 4 passes -> 64 rows
    const int pc4 = (t & 15) * 4;

    // contiguous valid chunk range: jc in [0, NSEQ-64]
    const int chlo = (i0 >= CTX) ? 0 : (CTX - i0 + 63) / 64;
    const int chhi = min(NCHUNK - 1, (NSEQ - 64 - i0 + CTX) / 64);

    // ---- prologue: prefetch first chunk ----
    {
        const int jc = i0 - CTX + chlo * 64;
        #pragma unroll
        for (int it = 0; it < 4; it++) {
            int r = pr + it * 16;
            cpa16(sb + RAWK + (uint32_t)(r * 64 + pc4) * 4,
                  &kg[(size_t)(jc + r) * DMODEL + hoff + pc4]);
            cpa16(sb + RAWV + (uint32_t)(r * 64 + pc4) * 4,
                  &vg[(size_t)(jc + r) * DMODEL + hoff + pc4]);
        }
        CPA_COMMIT();
    }

    // ---- load Q once: scale (incl. log2e), single fp16 ----
    for (int idx = t; idx < QT * 16; idx += 256) {
        int r = idx >> 4, c4 = (idx & 15) * 4;
        float4 q4 = *(const float4*)&qg[(size_t)(i0 + r) * DMODEL + hoff + c4];
        q4.x *= QSCALE; q4.y *= QSCALE; q4.z *= QSCALE; q4.w *= QSCALE;
        uint32_t boff = (uint32_t)(r * SP + c4) * 2;
        *(uint2*)(smem + QTI + boff) = make_uint2(pack_f16(q4.x, q4.y), pack_f16(q4.z, q4.w));
    }

    // ---- prologue convert: raw -> fp16 tiles (own bytes only) ----
    {
        CPA_WAIT0();
        const uint32_t kt = KT0 + (uint32_t)(chlo & 1) * KVTILE;
        const uint32_t vt = VT0 + (uint32_t)(chlo & 1) * KVTILE;
        #pragma unroll
        for (int it = 0; it < 4; it++) {
            int r = pr + it * 16;
            uint32_t roff = (uint32_t)(r * 64 + pc4) * 4;
            uint32_t boff = (uint32_t)(r * SP + pc4) * 2;
            float4 k4 = *(const float4*)(smem + RAWK + roff);
            *(uint2*)(smem + kt + boff) = make_uint2(pack_f16(k4.x, k4.y), pack_f16(k4.z, k4.w));
            float4 v4 = *(const float4*)(smem + RAWV + roff);
            *(uint2*)(smem + vt + boff) = make_uint2(pack_f16(v4.x, v4.y), pack_f16(v4.z, v4.w));
        }
    }
    __syncthreads();   // Q tile + first converts visible

    // ldmatrix per-lane byte offsets
    const int l = lane;
    const uint32_t aoffA = (uint32_t)(((wr * 16 + (l & 15)) * SP + (l >> 4) * 8) * 2);
    const uint32_t aoffB = (uint32_t)((((l & 7) + ((l >> 4) & 1) * 8) * SP
                                      + ((l >> 3) & 1) * 8) * 2);
    const uint32_t aoffV = (uint32_t)((((l & 7) + ((l >> 3) & 1) * 8) * SP
                                      + ((l >> 4) & 1) * 8) * 2);

    // ---- hoist Q fragments into registers (chunk-invariant) ----
    uint32_t aq[4][4];
    #pragma unroll
    for (int k = 0; k < 4; k++)
        ldsm4(aq[k], sb + QTI + aoffA + k * 32);

    float oacc[8][4];
    #pragma unroll
    for (int i = 0; i < 8; i++)
        #pragma unroll
        for (int j = 0; j < 4; j++) oacc[i][j] = 0.f;
    float l0 = 0.f, l1 = 0.f;

    const int ig0 = i0 + wr * 16 + g, ig1 = ig0 + 8;

    for (int ch = chlo; ch <= chhi; ch++) {
        const int b  = ch & 1;
        const int jc = i0 - CTX + ch * 64;

        // ---- prefetch chunk ch+1 (overlaps compute) ----
        if (ch < chhi) {
            const int jn = jc + 64;
            #pragma unroll
            for (int it = 0; it < 4; it++) {
                int r = pr + it * 16;
                cpa16(sb + RAWK + (uint32_t)(r * 64 + pc4) * 4,
                      &kg[(size_t)(jn + r) * DMODEL + hoff + pc4]);
                cpa16(sb + RAWV + (uint32_t)(r * 64 + pc4) * 4,
                      &vg[(size_t)(jn + r) * DMODEL + hoff + pc4]);
            }
            CPA_COMMIT();
        }

        // ---- warp-tile band intersection: keys [jc,jc+64) vs rows [wr*16, wr*16+16) ----
        const int doff = jc - i0;
        const bool active = (doff + 63 >= wr * 16 - CTX) && (doff <= wr * 16 + 15 + CTX);
        if (active) {
            const uint32_t ktb = sb + KT0 + (uint32_t)b * KVTILE;
            const uint32_t vtb = sb + VT0 + (uint32_t)b * KVTILE;

            // ---- GEMM1: S(16x64) = Q K^T (single fp16, Q frags hoisted) ----
            float sacc[8][4];
            #pragma unroll
            for (int i = 0; i < 8; i++)
                #pragma unroll
                for (int j = 0; j < 4; j++) sacc[i][j] = 0.f;

            #pragma unroll
            for (int k = 0; k < 4; k++) {
                #pragma unroll
                for (int nt2 = 0; nt2 < 4; nt2++) {
                    uint32_t bh[4];
                    ldsm4(bh, ktb + aoffB + nt2 * (16 * SP * 2) + k * 32);
                    mma16816(sacc[2 * nt2],     aq[k], bh);
                    mma16816(sacc[2 * nt2 + 1], aq[k], bh + 2);
                }
            }

            // ---- softmax: p = 2^s; mask only tiles straddling the band edge ----
            uint32_t pah[4][4];
            const bool fullband = (doff >= wr * 16 - 113) && (doff <= wr * 16 + 65);
            if (!fullband) {
                #pragma unroll
                for (int nt = 0; nt < 8; nt++) {
                    int jg0 = jc + nt * 8 + 2 * qa, jg1 = jg0 + 1;
                    float p00 = ((unsigned)(jg0 - (ig0 - CTX)) <= 2u * CTX) ? ex2a(sacc[nt][0]) : 0.f;
                    float p01 = ((unsigned)(jg1 - (ig0 - CTX)) <= 2u * CTX) ? ex2a(sacc[nt][1]) : 0.f;
                    float p10 = ((unsigned)(jg0 - (ig1 - CTX)) <= 2u * CTX) ? ex2a(sacc[nt][2]) : 0.f;
                    float p11 = ((unsigned)(jg1 - (ig1 - CTX)) <= 2u * CTX) ? ex2a(sacc[nt][3]) : 0.f;
                    l0 += p00 + p01; l1 += p10 + p11;
                    pah[nt >> 1][(nt & 1) * 2 + 0] = pack_f16(p00, p01);
                    pah[nt >> 1][(nt & 1) * 2 + 1] = pack_f16(p10, p11);
                }
            } else {
                #pragma unroll
                for (int nt = 0; nt < 8; nt++) {
                    float p00 = ex2a(sacc[nt][0]);
                    float p01 = ex2a(sacc[nt][1]);
                    float p10 = ex2a(sacc[nt][2]);
                    float p11 = ex2a(sacc[nt][3]);
                    l0 += p00 + p01; l1 += p10 + p11;
                    pah[nt >> 1][(nt & 1) * 2 + 0] = pack_f16(p00, p01);
                    pah[nt >> 1][(nt & 1) * 2 + 1] = pack_f16(p10, p11);
                }
            }

            // ---- GEMM2: O(16x64) += P V ----
            #pragma unroll
            for (int ks = 0; ks < 4; ks++) {
                #pragma unroll
                for (int nt2 = 0; nt2 < 4; nt2++) {
                    uint32_t vh[4];
                    ldsm4t(vh, vtb + aoffV + ks * (16 * SP * 2) + nt2 * 32);
                    mma16816(oacc[2 * nt2],     pah[ks], vh);
                    mma16816(oacc[2 * nt2 + 1], pah[ks], vh + 2);
                }
            }
        }

        // ---- convert next chunk raw -> tiles(b^1) (own bytes; self-visible) ----
        if (ch < chhi) {
            CPA_WAIT0();
            const uint32_t kt = KT0 + (uint32_t)(b ^ 1) * KVTILE;
            const uint32_t vt = VT0 + (uint32_t)(b ^ 1) * KVTILE;
            #pragma unroll
            for (int it = 0; it < 4; it++) {
                int r = pr + it * 16;
                uint32_t roff = (uint32_t)(r * 64 + pc4) * 4;
                uint32_t boff = (uint32_t)(r * SP + pc4) * 2;
                float4 k4 = *(const float4*)(smem + RAWK + roff);
                *(uint2*)(smem + kt + boff) = make_uint2(pack_f16(k4.x, k4.y),
                                                         pack_f16(k4.z, k4.w));
                float4 v4 = *(const float4*)(smem + RAWV + roff);
                *(uint2*)(smem + vt + boff) = make_uint2(pack_f16(v4.x, v4.y),
                                                         pack_f16(v4.z, v4.w));
            }
        }
        __syncthreads();   // converts visible; tile(b) reads done before overwrite
    }

    // ---- epilogue: in-warp row sums, normalize in regs ----
    l0 += __shfl_xor_sync(0xffffffffu, l0, 1);
    l0 += __shfl_xor_sync(0xffffffffu, l0, 2);
    l1 += __shfl_xor_sync(0xffffffffu, l1, 1);
    l1 += __shfl_xor_sync(0xffffffffu, l1, 2);
    const float inv0 = 1.0f / l0, inv1 = 1.0f / l1;

    __syncthreads();   // all warps done with K/V tiles before aliasing as OB

    float* Ob = (float*)(smem + OB);
    const int r0 = wr * 16 + g, r1 = r0 + 8;
    #pragma unroll
    for (int nt = 0; nt < 8; nt++) {
        int c = nt * 8 + 2 * qa;
        *(float2*)&Ob[r0 * OPS + c] = make_float2(oacc[nt][0] * inv0, oacc[nt][1] * inv0);
        *(float2*)&Ob[r1 * OPS + c] = make_float2(oacc[nt][2] * inv1, oacc[nt][3] * inv1);
    }
    __syncthreads();

    // ---- coalesced store ----
    for (int idx = t; idx < QT * 16; idx += 256) {
        int r = idx >> 4, c4 = (idx & 15) * 4;
        float4 o4 = *(const float4*)&Ob[r * OPS + c4];
        *(float4*)&og[(size_t)(i0 + r) * DMODEL + hoff + c4] = o4;
    }
}

extern "C" void kernel_launch(void* const* d_in, const int* in_sizes, int n_in,
                              void* d_out, int out_size) {
    (void)in_sizes; (void)n_in; (void)out_size;
    const float* q = (const float*)d_in[0];
    const float* k = (const float*)d_in[1];
    const float* v = (const float*)d_in[2];
    float* o = (float*)d_out;

    cudaFuncSetAttribute(sparse_attn_mma,
                         cudaFuncAttributeMaxDynamicSharedMemorySize, SMEM_BYTES);
    dim3 grid(NSEQ / QT, HEADS);
    sparse_attn_mma<<<grid, 256, SMEM_BYTES>>>(q, k, v, o);
}